// round 10
// baseline (speedup 1.0000x reference)
#include <cuda_runtime.h>
#include <cuda_bf16.h>
#include <math.h>
#include <stdint.h>

#define Bsz 8192
#define Tt  128
#define Do  5
#define OFF_H ((size_t)Bsz * Tt * Do)
#define OFF_C (OFF_H + (size_t)Bsz * 128)

__device__ float4 g_s2[Tt * 128];            // folded emb-BN affine (s0,s1,s2,_)
__device__ float g_bias[512];                // b_ih+b_hh permuted to n'=4j+gate
__device__ float g_woutT[640];               // W_out^T [j][f]
__device__ float g_y[(size_t)640 * Bsz];     // pre-BN y [t*5+f][row]
__device__ float g_ymean[640];
__device__ float g_yrstd[640];
// W panels: [mat(2)][kpanel(8)] x 32KB (hi 16K | lo 16K); 512 n' x 16 k each
__device__ __align__(16) char g_wp[16 * 32768];

#define SA_EH 0
#define SA_EL 16384
#define SA_HH 32768
#define SA_HL 49152
#define SB    65536
#define SWOUT 196608
#define SBIAS 199168
#define SMEMB 201216

__device__ __forceinline__ uint32_t s2u(const void* p) {
    uint32_t a;
    asm("{ .reg .u64 t; cvta.to.shared.u64 t, %1; cvt.u32.u64 %0, t; }" : "=r"(a) : "l"(p));
    return a;
}
__device__ __forceinline__ void ldsm4(uint32_t r[4], uint32_t a) {
    asm volatile("ldmatrix.sync.aligned.m8n8.x4.shared.b16 {%0,%1,%2,%3}, [%4];"
        : "=r"(r[0]), "=r"(r[1]), "=r"(r[2]), "=r"(r[3]) : "r"(a));
}
__device__ __forceinline__ void mma16816(float d[4], const uint32_t a[4], uint32_t b0, uint32_t b1) {
    asm volatile("mma.sync.aligned.m16n8k16.row.col.f32.bf16.bf16.f32 "
        "{%0,%1,%2,%3}, {%4,%5,%6,%7}, {%8,%9}, {%0,%1,%2,%3};"
        : "+f"(d[0]), "+f"(d[1]), "+f"(d[2]), "+f"(d[3])
        : "r"(a[0]), "r"(a[1]), "r"(a[2]), "r"(a[3]), "r"(b0), "r"(b1));
}
__device__ __forceinline__ uint32_t pkbf(float a, float b) {
    __nv_bfloat16 ha = __float2bfloat16(a), hb = __float2bfloat16(b);
    return (uint32_t)__bfloat16_as_ushort(ha) | ((uint32_t)__bfloat16_as_ushort(hb) << 16);
}
__device__ __forceinline__ void cpa16(uint32_t dst, const void* src) {
    asm volatile("cp.async.cg.shared.global [%0], [%1], 16;" :: "r"(dst), "l"(src));
}
#define CP_COMMIT() asm volatile("cp.async.commit_group;" ::: "memory")
#define CP_WAIT2()  asm volatile("cp.async.wait_group 2;" ::: "memory")

__global__ void k_emb_stats(const float* __restrict__ x, const float* __restrict__ W_emb,
                            const float* __restrict__ b_emb, const float* __restrict__ gamma,
                            const float* __restrict__ beta) {
    int t = blockIdx.x, tid = threadIdx.x;
    float m0 = 0.f, m1 = 0.f, m00 = 0.f, m11 = 0.f, m01 = 0.f;
    for (int b = tid; b < Bsz; b += 256) {
        size_t xi = ((size_t)b * Tt + t) * 2;
        float x0 = x[xi], x1 = x[xi + 1];
        m0 += x0; m1 += x1; m00 += x0 * x0; m11 += x1 * x1; m01 += x0 * x1;
    }
    const unsigned F = 0xffffffffu;
    #pragma unroll
    for (int o = 16; o; o >>= 1) {
        m0 += __shfl_xor_sync(F, m0, o); m1 += __shfl_xor_sync(F, m1, o);
        m00 += __shfl_xor_sync(F, m00, o); m11 += __shfl_xor_sync(F, m11, o);
        m01 += __shfl_xor_sync(F, m01, o);
    }
    __shared__ float sw[8][5], mom[5];
    int w = tid >> 5, l = tid & 31;
    if (l == 0) { sw[w][0] = m0; sw[w][1] = m1; sw[w][2] = m00; sw[w][3] = m11; sw[w][4] = m01; }
    __syncthreads();
    if (tid < 5) {
        float s = 0.f;
        #pragma unroll
        for (int i = 0; i < 8; i++) s += sw[i][tid];
        mom[tid] = s * (1.0f / Bsz);
    }
    __syncthreads();
    if (tid < 128) {
        float mx0 = mom[0], mx1 = mom[1];
        float vx0 = mom[2] - mx0 * mx0, vx1 = mom[3] - mx1 * mx1, cxy = mom[4] - mx0 * mx1;
        float w0 = W_emb[tid * 2], w1 = W_emb[tid * 2 + 1];
        float mu = w0 * mx0 + w1 * mx1 + b_emb[tid];
        float var = w0 * w0 * vx0 + 2.0f * w0 * w1 * cxy + w1 * w1 * vx1;
        float gr = gamma[tid] * rsqrtf(var + 1e-5f);
        g_s2[t * 128 + tid] = make_float4(gr * w0, gr * w1,
                                          gr * (b_emb[tid] - mu) + beta[tid], 0.f);
    }
}

__global__ void k_prep(const float* __restrict__ Wih, const float* __restrict__ Whh,
                       const float* __restrict__ bih, const float* __restrict__ bhh,
                       const float* __restrict__ Wout) {
    int id = blockIdx.x * 256 + threadIdx.x;  // 131072
    int mat = id >> 16, e = id & 65535;
    int np = e >> 7, k = e & 127;
    int src = ((np & 3) * 128 + (np >> 2)) * 128 + k;
    float wv = mat ? Whh[src] : Wih[src];
    __nv_bfloat16 hi = __float2bfloat16(wv);
    __nv_bfloat16 lo = __float2bfloat16(wv - __bfloat162float(hi));
    int kl = k & 15;
    int off = (mat * 8 + (k >> 4)) * 32768
            + ((np >> 3) << 8) + ((kl >> 3) << 7) + ((np & 7) << 4) + ((kl & 7) << 1);
    *(__nv_bfloat16*)(g_wp + off) = hi;
    *(__nv_bfloat16*)(g_wp + off + 16384) = lo;
    if (id < 512) {
        int orig = (id & 3) * 128 + (id >> 2);
        g_bias[id] = bih[orig] + bhh[orig];
    }
    if (id >= 1024 && id < 1664) {
        int idx = id - 1024;
        g_woutT[(idx & 127) * 5 + (idx >> 7)] = Wout[idx];
    }
}

// persistent recurrence: block = 64 rows x all 512 gates, 8 warps (warp: N=64)
__global__ void __launch_bounds__(256, 1) k_lstm(const float* __restrict__ x,
                                                 float* __restrict__ out) {
    extern __shared__ char sm[];
    uint32_t smb = s2u(sm);
    float* swout = (float*)(sm + SWOUT);
    float* Dst = (float*)sm;          // overlays e images after GEMM: 16 x 512
    int tid = threadIdx.x, lane = tid & 31, w = tid >> 5;
    int brow = blockIdx.x << 6;
    const unsigned F = 0xffffffffu;

    for (int i = tid; i < 640; i += 256) swout[i] = g_woutT[i];
    for (int i = tid; i < 512; i += 256) ((float*)(sm + SBIAS))[i] = g_bias[i];
    {
        uint4 z = make_uint4(0, 0, 0, 0);
        for (int i = tid; i < 2048; i += 256)   // zero h hi+lo (32KB at SA_HH)
            ((uint4*)(sm + SA_HH))[i] = z;
    }
    __syncthreads();

    auto issue = [&](int gp) {
        const char* src = g_wp + (size_t)(gp & 15) * 32768;
        uint32_t dst = smb + SB + (gp & 3) * 32768;
        #pragma unroll
        for (int q = 0; q < 8; q++)
            cpa16(dst + q * 4096 + tid * 16, src + q * 4096 + tid * 16);
        CP_COMMIT();
    };
    issue(0); issue(1); issue(2);

    int ar = (lane & 7) | (((lane >> 3) & 1) << 3);
    int akc = lane >> 4;
    int rA[4], rxA[4];
    #pragma unroll
    for (int mf = 0; mf < 4; mf++) { rA[mf] = (mf * 16 + ar) * 256; rxA[mf] = (mf * 16 + ar) & 7; }
    int wn0 = w << 6;
    int bnh = (lane >> 4) & 1, bkc = (lane >> 3) & 1;
    uint32_t offB[4];
    #pragma unroll
    for (int p = 0; p < 4; p++) {
        int r = wn0 + p * 16 + bnh * 8 + (lane & 7);
        offB[p] = ((r >> 3) << 8) + (bkc << 7) + ((r & 7) << 4);
    }

    float c[4][8];
    #pragma unroll
    for (int i = 0; i < 4; i++)
        #pragma unroll
        for (int j = 0; j < 8; j++) c[i][j] = 0.f;

    int erow = tid >> 2, eks = tid & 3;     // e-build mapping
    int r16 = tid >> 4, jl = tid & 15;      // cell mapping
    int rr = lane >> 2, cc2 = (lane & 3) << 1;

    for (int t = 0; t < Tt; t++) {
        {   // build e image (hi/lo) — same construction as R6 (proven)
            float2 xv = *(const float2*)&x[((size_t)(brow + erow) * Tt + t) * 2];
            #pragma unroll
            for (int cc = 0; cc < 4; cc++) {
                int k0 = eks * 32 + cc * 8;
                uint32_t wh[4], wl[4];
                #pragma unroll
                for (int q = 0; q < 4; q++) {
                    float4 sA = g_s2[t * 128 + k0 + q * 2];
                    float4 sB = g_s2[t * 128 + k0 + q * 2 + 1];
                    float e0 = fmaxf(fmaf(sA.x, xv.x, fmaf(sA.y, xv.y, sA.z)), 0.f);
                    float e1 = fmaxf(fmaf(sB.x, xv.x, fmaf(sB.y, xv.y, sB.z)), 0.f);
                    __nv_bfloat16 h0 = __float2bfloat16(e0), h1 = __float2bfloat16(e1);
                    wh[q] = (uint32_t)__bfloat16_as_ushort(h0) | ((uint32_t)__bfloat16_as_ushort(h1) << 16);
                    wl[q] = pkbf(e0 - __bfloat162float(h0), e1 - __bfloat162float(h1));
                }
                int kc = k0 >> 3;
                int off = erow * 256 + ((kc ^ (erow & 7)) << 4);
                *(uint4*)(sm + SA_EH + off) = make_uint4(wh[0], wh[1], wh[2], wh[3]);
                *(uint4*)(sm + SA_EL + off) = make_uint4(wl[0], wl[1], wl[2], wl[3]);
            }
        }

        float acc[4][8][4];
        #pragma unroll
        for (int i = 0; i < 4; i++)
            #pragma unroll
            for (int j = 0; j < 8; j++)
                #pragma unroll
                for (int q = 0; q < 4; q++) acc[i][j][q] = 0.f;

        for (int i = 0; i < 16; i++) {
            int g = t * 16 + i;
            CP_WAIT2();
            __syncthreads();
            if (g + 3 < Tt * 16) issue(g + 3);
            uint32_t aH = smb + (i < 8 ? SA_EH : SA_HH);
            uint32_t aL = aH + 16384;
            uint32_t bH = smb + SB + (g & 3) * 32768;
            uint32_t bL = bH + 16384;
            int kc2 = (i & 7) * 2;
            uint32_t ah[4][4], al[4][4], bh[4][4], bl[4][4];
            #pragma unroll
            for (int mf = 0; mf < 4; mf++) {
                uint32_t o = rA[mf] + (((kc2 + akc) ^ rxA[mf]) << 4);
                ldsm4(ah[mf], aH + o);
                ldsm4(al[mf], aL + o);
            }
            #pragma unroll
            for (int p = 0; p < 4; p++) { ldsm4(bh[p], bH + offB[p]); ldsm4(bl[p], bL + offB[p]); }
            #pragma unroll
            for (int mf = 0; mf < 4; mf++)
                #pragma unroll
                for (int nf = 0; nf < 8; nf++)
                    mma16816(acc[mf][nf], ah[mf], bh[nf >> 1][(nf & 1) * 2], bh[nf >> 1][(nf & 1) * 2 + 1]);
            #pragma unroll
            for (int mf = 0; mf < 4; mf++)
                #pragma unroll
                for (int nf = 0; nf < 8; nf++)
                    mma16816(acc[mf][nf], al[mf], bh[nf >> 1][(nf & 1) * 2], bh[nf >> 1][(nf & 1) * 2 + 1]);
            #pragma unroll
            for (int mf = 0; mf < 4; mf++)
                #pragma unroll
                for (int nf = 0; nf < 8; nf++)
                    mma16816(acc[mf][nf], ah[mf], bl[nf >> 1][(nf & 1) * 2], bl[nf >> 1][(nf & 1) * 2 + 1]);
        }
        __syncthreads();   // GEMM done: e images dead, h image dead -> stage/cell

        // ---- staged cell, per 16-row slab (R4-proven dataflow) ----
        for (int mf = 0; mf < 4; mf++) {
            #pragma unroll
            for (int nf = 0; nf < 8; nf++) {
                int cb = wn0 + nf * 8 + cc2;
                *(float2*)&Dst[rr * 512 + cb]       = make_float2(acc[mf][nf][0], acc[mf][nf][1]);
                *(float2*)&Dst[(rr + 8) * 512 + cb] = make_float2(acc[mf][nf][2], acc[mf][nf][3]);
            }
            __syncthreads();
            int rowg = mf * 16 + r16;
            float ya0 = 0.f, ya1 = 0.f, ya2 = 0.f, ya3 = 0.f, ya4 = 0.f;
            uint32_t whh[4], wll[4];
            #pragma unroll
            for (int jj = 0; jj < 8; jj += 2) {
                int j0 = jl * 8 + jj;
                float hn2[2], cn2[2];
                #pragma unroll
                for (int u = 0; u < 2; u++) {
                    int j = j0 + u;
                    float4 g4 = *(float4*)&Dst[r16 * 512 + 4 * j];
                    float4 bv = *(float4*)(sm + SBIAS + j * 16);
                    float gi = g4.x + bv.x, gf = g4.y + bv.y, gg = g4.z + bv.z, go = g4.w + bv.w;
                    float si = __fdividef(1.f, 1.f + __expf(-gi));
                    float sf = __fdividef(1.f, 1.f + __expf(-gf));
                    float tg = __fdividef(2.f, 1.f + __expf(-2.f * gg)) - 1.f;
                    float so = __fdividef(1.f, 1.f + __expf(-go));
                    float cn = sf * c[mf][jj + u] + si * tg;
                    float tc = __fdividef(2.f, 1.f + __expf(-2.f * cn)) - 1.f;
                    float hn = so * tc;
                    c[mf][jj + u] = cn;
                    hn2[u] = hn; cn2[u] = cn;
                    ya0 = fmaf(hn, swout[j * 5 + 0], ya0);
                    ya1 = fmaf(hn, swout[j * 5 + 1], ya1);
                    ya2 = fmaf(hn, swout[j * 5 + 2], ya2);
                    ya3 = fmaf(hn, swout[j * 5 + 3], ya3);
                    ya4 = fmaf(hn, swout[j * 5 + 4], ya4);
                    if (t == Tt - 1) {
                        out[OFF_H + (size_t)(brow + rowg) * 128 + j] = hn;
                        out[OFF_C + (size_t)(brow + rowg) * 128 + j] = cn;
                    }
                }
                __nv_bfloat16 h0 = __float2bfloat16(hn2[0]), h1 = __float2bfloat16(hn2[1]);
                whh[jj >> 1] = (uint32_t)__bfloat16_as_ushort(h0) | ((uint32_t)__bfloat16_as_ushort(h1) << 16);
                wll[jj >> 1] = pkbf(hn2[0] - __bfloat162float(h0), hn2[1] - __bfloat162float(h1));
            }
            // thread owns chunk jl of row rowg: one uint4 store, same scheme as e build
            {
                int off = rowg * 256 + ((jl ^ (rowg & 7)) << 4);
                *(uint4*)(sm + SA_HH + off) = make_uint4(whh[0], whh[1], whh[2], whh[3]);
                *(uint4*)(sm + SA_HL + off) = make_uint4(wll[0], wll[1], wll[2], wll[3]);
            }
            // reduce y over the 16 lanes sharing this row
            #pragma unroll
            for (int o2 = 1; o2 <= 8; o2 <<= 1) {
                ya0 += __shfl_xor_sync(F, ya0, o2);
                ya1 += __shfl_xor_sync(F, ya1, o2);
                ya2 += __shfl_xor_sync(F, ya2, o2);
                ya3 += __shfl_xor_sync(F, ya3, o2);
                ya4 += __shfl_xor_sync(F, ya4, o2);
            }
            if ((lane & 15) == 0) {
                size_t yb = (size_t)(t * 5) * 8192 + brow + rowg;
                g_y[yb] = ya0; g_y[yb + 8192] = ya1; g_y[yb + 16384] = ya2;
                g_y[yb + 24576] = ya3; g_y[yb + 32768] = ya4;
            }
            __syncthreads();
        }
    }
}

__global__ void k_ystats() {
    int tf = blockIdx.x, tid = threadIdx.x;
    float s = 0.f, q = 0.f;
    for (int b = tid; b < Bsz; b += 256) {
        float v = g_y[(size_t)tf * 8192 + b];
        s += v; q += v * v;
    }
    const unsigned F = 0xffffffffu;
    #pragma unroll
    for (int o = 16; o; o >>= 1) { s += __shfl_xor_sync(F, s, o); q += __shfl_xor_sync(F, q, o); }
    __shared__ float sws[8], swq[8];
    int w = tid >> 5;
    if ((tid & 31) == 0) { sws[w] = s; swq[w] = q; }
    __syncthreads();
    if (tid == 0) {
        float S = 0.f, Q = 0.f;
        #pragma unroll
        for (int i = 0; i < 8; i++) { S += sws[i]; Q += swq[i]; }
        float mean = S * (1.0f / Bsz);
        g_ymean[tf] = mean;
        g_yrstd[tf] = rsqrtf(Q * (1.0f / Bsz) - mean * mean + 1e-5f);
    }
}
__global__ void k_ynorm(const float* __restrict__ gamma, const float* __restrict__ beta,
                        float* __restrict__ out) {
    size_t i = (size_t)blockIdx.x * 256 + threadIdx.x;
    if (i >= (size_t)Bsz * Tt * Do) return;
    size_t b = i / 640;
    int tf = (int)(i % 640);
    int f = tf % 5;
    float v = g_y[(size_t)tf * 8192 + b];
    out[i] = gamma[f] * (v - g_ymean[tf]) * g_yrstd[tf] + beta[f];
}

extern "C" void kernel_launch(void* const* d_in, const int* in_sizes, int n_in,
                              void* d_out, int out_size) {
    const float* x         = (const float*)d_in[0];
    const float* W_emb     = (const float*)d_in[1];
    const float* b_emb     = (const float*)d_in[2];
    const float* gamma_emb = (const float*)d_in[3];
    const float* beta_emb  = (const float*)d_in[4];
    const float* W_ih      = (const float*)d_in[5];
    const float* b_ih      = (const float*)d_in[6];
    const float* W_hh      = (const float*)d_in[7];
    const float* b_hh      = (const float*)d_in[8];
    const float* W_out     = (const float*)d_in[9];
    // d_in[10] = b_out: cancels exactly inside the output BatchNorm.
    const float* gamma_out = (const float*)d_in[11];
    const float* beta_out  = (const float*)d_in[12];
    float* out = (float*)d_out;

    cudaFuncSetAttribute(k_lstm, cudaFuncAttributeMaxDynamicSharedMemorySize, SMEMB);

    k_emb_stats<<<Tt, 256>>>(x, W_emb, b_emb, gamma_emb, beta_emb);
    k_prep<<<512, 256>>>(W_ih, W_hh, b_ih, b_hh, W_out);
    k_lstm<<<128, 256, SMEMB>>>(x, out);
    k_ystats<<<640, 256>>>();
    int n = Bsz * Tt * Do;
    k_ynorm<<<(n + 255) / 256, 256>>>(gamma_out, beta_out, out);
}

// round 11
// speedup vs baseline: 4.7320x; 4.7320x over previous
#include <cuda_runtime.h>
#include <cuda_bf16.h>
#include <math.h>
#include <stdint.h>

#define Bsz 8192
#define Tt  128
#define Do  5
#define OFF_H ((size_t)Bsz * Tt * Do)
#define OFF_C (OFF_H + (size_t)Bsz * 128)

__device__ float4 g_s2[Tt * 128];            // folded emb-BN affine (s0,s1,s2,_)
__device__ float g_bias[512];                // b_ih+b_hh permuted to n'=4j+gate
__device__ float g_woutT[640];               // W_out^T [j][f]
__device__ float g_y[(size_t)640 * Bsz];     // pre-BN y [t*5+f][row]
__device__ float g_ymean[640];
__device__ float g_yrstd[640];
// W panels: [mat(2)][kpanel(8)] x 32KB (hi 16K | lo 16K); 512 n' x 16 k each
__device__ __align__(16) char g_wp[16 * 32768];

#define SA_EH 0
#define SA_EL 16384
#define SA_HH 32768
#define SA_HL 49152
#define SB    65536
#define SWOUT 196608
#define SBIAS 199168
#define SMEMB 201216

__device__ __forceinline__ uint32_t s2u(const void* p) {
    uint32_t a;
    asm("{ .reg .u64 t; cvta.to.shared.u64 t, %1; cvt.u32.u64 %0, t; }" : "=r"(a) : "l"(p));
    return a;
}
__device__ __forceinline__ void ldsm4(uint32_t r[4], uint32_t a) {
    asm volatile("ldmatrix.sync.aligned.m8n8.x4.shared.b16 {%0,%1,%2,%3}, [%4];"
        : "=r"(r[0]), "=r"(r[1]), "=r"(r[2]), "=r"(r[3]) : "r"(a));
}
__device__ __forceinline__ void mma16816(float d[4], const uint32_t a[4], uint32_t b0, uint32_t b1) {
    asm volatile("mma.sync.aligned.m16n8k16.row.col.f32.bf16.bf16.f32 "
        "{%0,%1,%2,%3}, {%4,%5,%6,%7}, {%8,%9}, {%0,%1,%2,%3};"
        : "+f"(d[0]), "+f"(d[1]), "+f"(d[2]), "+f"(d[3])
        : "r"(a[0]), "r"(a[1]), "r"(a[2]), "r"(a[3]), "r"(b0), "r"(b1));
}
__device__ __forceinline__ uint32_t pkbf(float a, float b) {
    __nv_bfloat16 ha = __float2bfloat16(a), hb = __float2bfloat16(b);
    return (uint32_t)__bfloat16_as_ushort(ha) | ((uint32_t)__bfloat16_as_ushort(hb) << 16);
}
__device__ __forceinline__ void cpa16(uint32_t dst, const void* src) {
    asm volatile("cp.async.cg.shared.global [%0], [%1], 16;" :: "r"(dst), "l"(src));
}
#define CP_COMMIT() asm volatile("cp.async.commit_group;" ::: "memory")
#define CP_WAIT2()  asm volatile("cp.async.wait_group 2;" ::: "memory")

__global__ void k_emb_stats(const float* __restrict__ x, const float* __restrict__ W_emb,
                            const float* __restrict__ b_emb, const float* __restrict__ gamma,
                            const float* __restrict__ beta) {
    int t = blockIdx.x, tid = threadIdx.x;
    float m0 = 0.f, m1 = 0.f, m00 = 0.f, m11 = 0.f, m01 = 0.f;
    for (int b = tid; b < Bsz; b += 256) {
        size_t xi = ((size_t)b * Tt + t) * 2;
        float x0 = x[xi], x1 = x[xi + 1];
        m0 += x0; m1 += x1; m00 += x0 * x0; m11 += x1 * x1; m01 += x0 * x1;
    }
    const unsigned F = 0xffffffffu;
    #pragma unroll
    for (int o = 16; o; o >>= 1) {
        m0 += __shfl_xor_sync(F, m0, o); m1 += __shfl_xor_sync(F, m1, o);
        m00 += __shfl_xor_sync(F, m00, o); m11 += __shfl_xor_sync(F, m11, o);
        m01 += __shfl_xor_sync(F, m01, o);
    }
    __shared__ float sw[8][5], mom[5];
    int w = tid >> 5, l = tid & 31;
    if (l == 0) { sw[w][0] = m0; sw[w][1] = m1; sw[w][2] = m00; sw[w][3] = m11; sw[w][4] = m01; }
    __syncthreads();
    if (tid < 5) {
        float s = 0.f;
        #pragma unroll
        for (int i = 0; i < 8; i++) s += sw[i][tid];
        mom[tid] = s * (1.0f / Bsz);
    }
    __syncthreads();
    if (tid < 128) {
        float mx0 = mom[0], mx1 = mom[1];
        float vx0 = mom[2] - mx0 * mx0, vx1 = mom[3] - mx1 * mx1, cxy = mom[4] - mx0 * mx1;
        float w0 = W_emb[tid * 2], w1 = W_emb[tid * 2 + 1];
        float mu = w0 * mx0 + w1 * mx1 + b_emb[tid];
        float var = w0 * w0 * vx0 + 2.0f * w0 * w1 * cxy + w1 * w1 * vx1;
        float gr = gamma[tid] * rsqrtf(var + 1e-5f);
        g_s2[t * 128 + tid] = make_float4(gr * w0, gr * w1,
                                          gr * (b_emb[tid] - mu) + beta[tid], 0.f);
    }
}

__global__ void k_prep(const float* __restrict__ Wih, const float* __restrict__ Whh,
                       const float* __restrict__ bih, const float* __restrict__ bhh,
                       const float* __restrict__ Wout) {
    int id = blockIdx.x * 256 + threadIdx.x;  // 131072
    int mat = id >> 16, e = id & 65535;
    int np = e >> 7, k = e & 127;
    int src = ((np & 3) * 128 + (np >> 2)) * 128 + k;
    float wv = mat ? Whh[src] : Wih[src];
    __nv_bfloat16 hi = __float2bfloat16(wv);
    __nv_bfloat16 lo = __float2bfloat16(wv - __bfloat162float(hi));
    int kl = k & 15;
    int off = (mat * 8 + (k >> 4)) * 32768
            + ((np >> 3) << 8) + ((kl >> 3) << 7) + ((np & 7) << 4) + ((kl & 7) << 1);
    *(__nv_bfloat16*)(g_wp + off) = hi;
    *(__nv_bfloat16*)(g_wp + off + 16384) = lo;
    if (id < 512) {
        int orig = (id & 3) * 128 + (id >> 2);
        g_bias[id] = bih[orig] + bhh[orig];
    }
    if (id >= 1024 && id < 1664) {
        int idx = id - 1024;
        g_woutT[(idx & 127) * 5 + (idx >> 7)] = Wout[idx];
    }
}

// persistent recurrence: block = 64 rows x 512 gates, 16 warps (warp tile 64x32)
__global__ void __launch_bounds__(512, 1) k_lstm(const float* __restrict__ x,
                                                 float* __restrict__ out) {
    extern __shared__ char sm[];
    uint32_t smb = s2u(sm);
    float* swout = (float*)(sm + SWOUT);
    float* Dst = (float*)sm;          // overlays e images after GEMM: 16 x 512
    int tid = threadIdx.x, lane = tid & 31, w = tid >> 5;   // w in 0..15
    int brow = blockIdx.x << 6;
    const unsigned F = 0xffffffffu;

    for (int i = tid; i < 640; i += 512) swout[i] = g_woutT[i];
    if (tid < 512) ((float*)(sm + SBIAS))[tid] = g_bias[tid];
    {
        uint4 z = make_uint4(0, 0, 0, 0);
        for (int i = tid; i < 2048; i += 512)   // zero h hi+lo (32KB)
            ((uint4*)(sm + SA_HH))[i] = z;
    }
    __syncthreads();

    auto issue = [&](int gp) {
        const char* src = g_wp + (size_t)(gp & 15) * 32768;
        uint32_t dst = smb + SB + (gp & 3) * 32768;
        #pragma unroll
        for (int q = 0; q < 4; q++)
            cpa16(dst + q * 8192 + tid * 16, src + q * 8192 + tid * 16);
        CP_COMMIT();
    };
    issue(0); issue(1); issue(2);

    int ar = (lane & 7) | (((lane >> 3) & 1) << 3);
    int akc = lane >> 4;
    int rx = ar & 7;                      // rxA constant across mf (mf*16 % 8 == 0)
    int wn0 = w << 5;
    int bnh = (lane >> 4) & 1, bkc = (lane >> 3) & 1;
    uint32_t offB[2];
    #pragma unroll
    for (int p = 0; p < 2; p++) {
        int r = wn0 + p * 16 + bnh * 8 + (lane & 7);
        offB[p] = ((r >> 3) << 8) + (bkc << 7) + ((r & 7) << 4);
    }

    float c[4][4];
    #pragma unroll
    for (int i = 0; i < 4; i++)
        #pragma unroll
        for (int j = 0; j < 4; j++) c[i][j] = 0.f;

    int erow = tid >> 3, eks = tid & 7;   // e-build: 64 rows x 8 k-slices

    for (int t = 0; t < Tt; t++) {
        {   // build e image (hi/lo)
            float2 xv = *(const float2*)&x[((size_t)(brow + erow) * Tt + t) * 2];
            #pragma unroll
            for (int cc = 0; cc < 2; cc++) {
                int kc = eks * 2 + cc;
                int k0 = kc * 8;
                uint32_t wh[4], wl[4];
                #pragma unroll
                for (int q = 0; q < 4; q++) {
                    float4 sA = g_s2[t * 128 + k0 + q * 2];
                    float4 sB = g_s2[t * 128 + k0 + q * 2 + 1];
                    float e0 = fmaxf(fmaf(sA.x, xv.x, fmaf(sA.y, xv.y, sA.z)), 0.f);
                    float e1 = fmaxf(fmaf(sB.x, xv.x, fmaf(sB.y, xv.y, sB.z)), 0.f);
                    __nv_bfloat16 h0 = __float2bfloat16(e0), h1 = __float2bfloat16(e1);
                    wh[q] = (uint32_t)__bfloat16_as_ushort(h0) | ((uint32_t)__bfloat16_as_ushort(h1) << 16);
                    wl[q] = pkbf(e0 - __bfloat162float(h0), e1 - __bfloat162float(h1));
                }
                int off = erow * 256 + ((kc ^ (erow & 7)) << 4);
                *(uint4*)(sm + SA_EH + off) = make_uint4(wh[0], wh[1], wh[2], wh[3]);
                *(uint4*)(sm + SA_EL + off) = make_uint4(wl[0], wl[1], wl[2], wl[3]);
            }
        }

        float acc[4][4][4];
        #pragma unroll
        for (int i = 0; i < 4; i++)
            #pragma unroll
            for (int j = 0; j < 4; j++)
                #pragma unroll
                for (int q = 0; q < 4; q++) acc[i][j][q] = 0.f;

        for (int i = 0; i < 16; i++) {
            int g = t * 16 + i;
            CP_WAIT2();
            __syncthreads();
            if (g + 3 < Tt * 16) issue(g + 3);
            uint32_t aH = smb + (i < 8 ? SA_EH : SA_HH);
            uint32_t bH = smb + SB + (g & 3) * 32768;
            int kc2 = (i & 7) * 2;
            uint32_t aoff = ar * 256 + (((kc2 + akc) ^ rx) << 4);
            // pass 1: A_hi x B_hi
            uint32_t ah[4][4], bh[2][4];
            #pragma unroll
            for (int mf = 0; mf < 4; mf++) ldsm4(ah[mf], aH + aoff + mf * 4096);
            #pragma unroll
            for (int p = 0; p < 2; p++) ldsm4(bh[p], bH + offB[p]);
            #pragma unroll
            for (int mf = 0; mf < 4; mf++)
                #pragma unroll
                for (int nf = 0; nf < 4; nf++)
                    mma16816(acc[mf][nf], ah[mf], bh[nf >> 1][(nf & 1) * 2], bh[nf >> 1][(nf & 1) * 2 + 1]);
            // pass 2: A_lo x B_hi
            {
                uint32_t al[4][4];
                #pragma unroll
                for (int mf = 0; mf < 4; mf++) ldsm4(al[mf], aH + 16384 + aoff + mf * 4096);
                #pragma unroll
                for (int mf = 0; mf < 4; mf++)
                    #pragma unroll
                    for (int nf = 0; nf < 4; nf++)
                        mma16816(acc[mf][nf], al[mf], bh[nf >> 1][(nf & 1) * 2], bh[nf >> 1][(nf & 1) * 2 + 1]);
            }
            // pass 3: A_hi x B_lo
            {
                uint32_t bl[2][4];
                #pragma unroll
                for (int p = 0; p < 2; p++) ldsm4(bl[p], bH + 16384 + offB[p]);
                #pragma unroll
                for (int mf = 0; mf < 4; mf++)
                    #pragma unroll
                    for (int nf = 0; nf < 4; nf++)
                        mma16816(acc[mf][nf], ah[mf], bl[nf >> 1][(nf & 1) * 2], bl[nf >> 1][(nf & 1) * 2 + 1]);
            }
        }
        __syncthreads();   // GEMM done: e/h images dead -> stage/cell

        int rr = lane >> 2, cc2 = (lane & 3) << 1;
        #pragma unroll
        for (int mf = 0; mf < 4; mf++) {
            #pragma unroll
            for (int nf = 0; nf < 4; nf++) {
                int cb = wn0 + nf * 8 + cc2;
                *(float2*)&Dst[rr * 512 + cb]       = make_float2(acc[mf][nf][0], acc[mf][nf][1]);
                *(float2*)&Dst[(rr + 8) * 512 + cb] = make_float2(acc[mf][nf][2], acc[mf][nf][3]);
            }
            __syncthreads();
            int rowg = mf * 16 + w;
            float ya0 = 0.f, ya1 = 0.f, ya2 = 0.f, ya3 = 0.f, ya4 = 0.f;
            float hn4[4];
            int j0 = lane * 4;
            #pragma unroll
            for (int u = 0; u < 4; u++) {
                int j = j0 + u;
                float4 g4 = *(float4*)&Dst[w * 512 + 4 * j];
                float4 bv = *(float4*)(sm + SBIAS + j * 16);
                float gi = g4.x + bv.x, gf = g4.y + bv.y, gg = g4.z + bv.z, go = g4.w + bv.w;
                float si = __fdividef(1.f, 1.f + __expf(-gi));
                float sf = __fdividef(1.f, 1.f + __expf(-gf));
                float tg = __fdividef(2.f, 1.f + __expf(-2.f * gg)) - 1.f;
                float so = __fdividef(1.f, 1.f + __expf(-go));
                float cn = sf * c[mf][u] + si * tg;
                float tc = __fdividef(2.f, 1.f + __expf(-2.f * cn)) - 1.f;
                float hn = so * tc;
                c[mf][u] = cn;
                hn4[u] = hn;
                ya0 = fmaf(hn, swout[j * 5 + 0], ya0);
                ya1 = fmaf(hn, swout[j * 5 + 1], ya1);
                ya2 = fmaf(hn, swout[j * 5 + 2], ya2);
                ya3 = fmaf(hn, swout[j * 5 + 3], ya3);
                ya4 = fmaf(hn, swout[j * 5 + 4], ya4);
                if (t == Tt - 1) {
                    out[OFF_H + (size_t)(brow + rowg) * 128 + j] = hn;
                    out[OFF_C + (size_t)(brow + rowg) * 128 + j] = cn;
                }
            }
            {   // thread owns 8 bytes (half a 16B chunk) of row rowg's h image
                __nv_bfloat16 h0 = __float2bfloat16(hn4[0]), h1 = __float2bfloat16(hn4[1]);
                __nv_bfloat16 h2 = __float2bfloat16(hn4[2]), h3 = __float2bfloat16(hn4[3]);
                uint2 wh = make_uint2(
                    (uint32_t)__bfloat16_as_ushort(h0) | ((uint32_t)__bfloat16_as_ushort(h1) << 16),
                    (uint32_t)__bfloat16_as_ushort(h2) | ((uint32_t)__bfloat16_as_ushort(h3) << 16));
                uint2 wl = make_uint2(
                    pkbf(hn4[0] - __bfloat162float(h0), hn4[1] - __bfloat162float(h1)),
                    pkbf(hn4[2] - __bfloat162float(h2), hn4[3] - __bfloat162float(h3)));
                int kc = lane >> 1;
                int off = rowg * 256 + ((kc ^ (rowg & 7)) << 4) + (lane & 1) * 8;
                *(uint2*)(sm + SA_HH + off) = wh;
                *(uint2*)(sm + SA_HL + off) = wl;
            }
            #pragma unroll
            for (int o2 = 1; o2 <= 16; o2 <<= 1) {
                ya0 += __shfl_xor_sync(F, ya0, o2);
                ya1 += __shfl_xor_sync(F, ya1, o2);
                ya2 += __shfl_xor_sync(F, ya2, o2);
                ya3 += __shfl_xor_sync(F, ya3, o2);
                ya4 += __shfl_xor_sync(F, ya4, o2);
            }
            if (lane == 0) {
                size_t yb = (size_t)(t * 5) * 8192 + brow + rowg;
                g_y[yb] = ya0; g_y[yb + 8192] = ya1; g_y[yb + 16384] = ya2;
                g_y[yb + 24576] = ya3; g_y[yb + 32768] = ya4;
            }
            __syncthreads();
        }
    }
}

__global__ void k_ystats() {
    int tf = blockIdx.x, tid = threadIdx.x;
    float s = 0.f, q = 0.f;
    for (int b = tid; b < Bsz; b += 256) {
        float v = g_y[(size_t)tf * 8192 + b];
        s += v; q += v * v;
    }
    const unsigned F = 0xffffffffu;
    #pragma unroll
    for (int o = 16; o; o >>= 1) { s += __shfl_xor_sync(F, s, o); q += __shfl_xor_sync(F, q, o); }
    __shared__ float sws[8], swq[8];
    int w = tid >> 5;
    if ((tid & 31) == 0) { sws[w] = s; swq[w] = q; }
    __syncthreads();
    if (tid == 0) {
        float S = 0.f, Q = 0.f;
        #pragma unroll
        for (int i = 0; i < 8; i++) { S += sws[i]; Q += swq[i]; }
        float mean = S * (1.0f / Bsz);
        g_ymean[tf] = mean;
        g_yrstd[tf] = rsqrtf(Q * (1.0f / Bsz) - mean * mean + 1e-5f);
    }
}
__global__ void k_ynorm(const float* __restrict__ gamma, const float* __restrict__ beta,
                        float* __restrict__ out) {
    size_t i = (size_t)blockIdx.x * 256 + threadIdx.x;
    if (i >= (size_t)Bsz * Tt * Do) return;
    size_t b = i / 640;
    int tf = (int)(i % 640);
    int f = tf % 5;
    float v = g_y[(size_t)tf * 8192 + b];
    out[i] = gamma[f] * (v - g_ymean[tf]) * g_yrstd[tf] + beta[f];
}

extern "C" void kernel_launch(void* const* d_in, const int* in_sizes, int n_in,
                              void* d_out, int out_size) {
    const float* x         = (const float*)d_in[0];
    const float* W_emb     = (const float*)d_in[1];
    const float* b_emb     = (const float*)d_in[2];
    const float* gamma_emb = (const float*)d_in[3];
    const float* beta_emb  = (const float*)d_in[4];
    const float* W_ih      = (const float*)d_in[5];
    const float* b_ih      = (const float*)d_in[6];
    const float* W_hh      = (const float*)d_in[7];
    const float* b_hh      = (const float*)d_in[8];
    const float* W_out     = (const float*)d_in[9];
    // d_in[10] = b_out: cancels exactly inside the output BatchNorm.
    const float* gamma_out = (const float*)d_in[11];
    const float* beta_out  = (const float*)d_in[12];
    float* out = (float*)d_out;

    cudaFuncSetAttribute(k_lstm, cudaFuncAttributeMaxDynamicSharedMemorySize, SMEMB);

    k_emb_stats<<<Tt, 256>>>(x, W_emb, b_emb, gamma_emb, beta_emb);
    k_prep<<<512, 256>>>(W_ih, W_hh, b_ih, b_hh, W_out);
    k_lstm<<<128, 512, SMEMB>>>(x, out);
    k_ystats<<<640, 256>>>();
    int n = Bsz * Tt * Do;
    k_ynorm<<<(n + 255) / 256, 256>>>(gamma_out, beta_out, out);
}

// round 12
// speedup vs baseline: 4.9492x; 1.0459x over previous
#include <cuda_runtime.h>
#include <cuda_bf16.h>
#include <math.h>
#include <stdint.h>

#define Bsz 8192
#define Tt  128
#define Do  5
#define OFF_H ((size_t)Bsz * Tt * Do)
#define OFF_C (OFF_H + (size_t)Bsz * 128)

__device__ float4 g_s2[Tt * 128];            // folded emb-BN affine (s0,s1,s2,_)
__device__ float g_bias[512];                // b_ih+b_hh permuted to n'=4j+gate
__device__ float g_woutT[640];               // W_out^T [j][f]
__device__ float g_y[(size_t)640 * Bsz];     // pre-BN y [t*5+f][row]
__device__ float g_ymean[640];
__device__ float g_yrstd[640];
// W panels: [mat(2)][kpanel(8)] x 32KB (hi 16K | lo 16K); 512 n' x 16 k each
__device__ __align__(16) char g_wp[16 * 32768];

#define SA_EH 0
#define SA_EL 16384
#define SA_HH 32768
#define SA_HL 49152
#define SB    65536
#define SWOUT 196608
#define SBIAS 199168
#define SMEMB 201216

__device__ __forceinline__ uint32_t s2u(const void* p) {
    uint32_t a;
    asm("{ .reg .u64 t; cvta.to.shared.u64 t, %1; cvt.u32.u64 %0, t; }" : "=r"(a) : "l"(p));
    return a;
}
__device__ __forceinline__ void ldsm4(uint32_t r[4], uint32_t a) {
    asm volatile("ldmatrix.sync.aligned.m8n8.x4.shared.b16 {%0,%1,%2,%3}, [%4];"
        : "=r"(r[0]), "=r"(r[1]), "=r"(r[2]), "=r"(r[3]) : "r"(a));
}
__device__ __forceinline__ void mma16816(float d[4], const uint32_t a[4], uint32_t b0, uint32_t b1) {
    asm volatile("mma.sync.aligned.m16n8k16.row.col.f32.bf16.bf16.f32 "
        "{%0,%1,%2,%3}, {%4,%5,%6,%7}, {%8,%9}, {%0,%1,%2,%3};"
        : "+f"(d[0]), "+f"(d[1]), "+f"(d[2]), "+f"(d[3])
        : "r"(a[0]), "r"(a[1]), "r"(a[2]), "r"(a[3]), "r"(b0), "r"(b1));
}
__device__ __forceinline__ uint32_t pkbf(float a, float b) {
    __nv_bfloat16 ha = __float2bfloat16(a), hb = __float2bfloat16(b);
    return (uint32_t)__bfloat16_as_ushort(ha) | ((uint32_t)__bfloat16_as_ushort(hb) << 16);
}
__device__ __forceinline__ void cpa16(uint32_t dst, const void* src) {
    asm volatile("cp.async.cg.shared.global [%0], [%1], 16;" :: "r"(dst), "l"(src));
}
#define CP_COMMIT() asm volatile("cp.async.commit_group;" ::: "memory")
#define CP_WAIT0()  asm volatile("cp.async.wait_group 0;" ::: "memory")

__global__ void k_emb_stats(const float* __restrict__ x, const float* __restrict__ W_emb,
                            const float* __restrict__ b_emb, const float* __restrict__ gamma,
                            const float* __restrict__ beta) {
    int t = blockIdx.x, tid = threadIdx.x;
    float m0 = 0.f, m1 = 0.f, m00 = 0.f, m11 = 0.f, m01 = 0.f;
    for (int b = tid; b < Bsz; b += 256) {
        size_t xi = ((size_t)b * Tt + t) * 2;
        float x0 = x[xi], x1 = x[xi + 1];
        m0 += x0; m1 += x1; m00 += x0 * x0; m11 += x1 * x1; m01 += x0 * x1;
    }
    const unsigned F = 0xffffffffu;
    #pragma unroll
    for (int o = 16; o; o >>= 1) {
        m0 += __shfl_xor_sync(F, m0, o); m1 += __shfl_xor_sync(F, m1, o);
        m00 += __shfl_xor_sync(F, m00, o); m11 += __shfl_xor_sync(F, m11, o);
        m01 += __shfl_xor_sync(F, m01, o);
    }
    __shared__ float sw[8][5], mom[5];
    int w = tid >> 5, l = tid & 31;
    if (l == 0) { sw[w][0] = m0; sw[w][1] = m1; sw[w][2] = m00; sw[w][3] = m11; sw[w][4] = m01; }
    __syncthreads();
    if (tid < 5) {
        float s = 0.f;
        #pragma unroll
        for (int i = 0; i < 8; i++) s += sw[i][tid];
        mom[tid] = s * (1.0f / Bsz);
    }
    __syncthreads();
    if (tid < 128) {
        float mx0 = mom[0], mx1 = mom[1];
        float vx0 = mom[2] - mx0 * mx0, vx1 = mom[3] - mx1 * mx1, cxy = mom[4] - mx0 * mx1;
        float w0 = W_emb[tid * 2], w1 = W_emb[tid * 2 + 1];
        float mu = w0 * mx0 + w1 * mx1 + b_emb[tid];
        float var = w0 * w0 * vx0 + 2.0f * w0 * w1 * cxy + w1 * w1 * vx1;
        float gr = gamma[tid] * rsqrtf(var + 1e-5f);
        g_s2[t * 128 + tid] = make_float4(gr * w0, gr * w1,
                                          gr * (b_emb[tid] - mu) + beta[tid], 0.f);
    }
}

__global__ void k_prep(const float* __restrict__ Wih, const float* __restrict__ Whh,
                       const float* __restrict__ bih, const float* __restrict__ bhh,
                       const float* __restrict__ Wout) {
    int id = blockIdx.x * 256 + threadIdx.x;  // 131072
    int mat = id >> 16, e = id & 65535;
    int np = e >> 7, k = e & 127;
    int src = ((np & 3) * 128 + (np >> 2)) * 128 + k;
    float wv = mat ? Whh[src] : Wih[src];
    __nv_bfloat16 hi = __float2bfloat16(wv);
    __nv_bfloat16 lo = __float2bfloat16(wv - __bfloat162float(hi));
    int kl = k & 15;
    int off = (mat * 8 + (k >> 4)) * 32768
            + ((np >> 3) << 8) + ((kl >> 3) << 7) + ((np & 7) << 4) + ((kl & 7) << 1);
    *(__nv_bfloat16*)(g_wp + off) = hi;
    *(__nv_bfloat16*)(g_wp + off + 16384) = lo;
    if (id < 512) {
        int orig = (id & 3) * 128 + (id >> 2);
        g_bias[id] = bih[orig] + bhh[orig];
    }
    if (id >= 1024 && id < 1664) {
        int idx = id - 1024;
        g_woutT[(idx & 127) * 5 + (idx >> 7)] = Wout[idx];
    }
}

__global__ void k_nop() {}

// persistent recurrence: block = 64 rows x 512 gates, 16 warps (warp tile 64x32)
__global__ void __launch_bounds__(512, 1) k_lstm(const float* __restrict__ x,
                                                 float* __restrict__ out) {
    extern __shared__ char sm[];
    uint32_t smb = s2u(sm);
    float* swout = (float*)(sm + SWOUT);
    int tid = threadIdx.x, lane = tid & 31, w = tid >> 5;   // w in 0..15
    int brow = blockIdx.x << 6;
    const unsigned F = 0xffffffffu;

    for (int i = tid; i < 640; i += 512) swout[i] = g_woutT[i];
    if (tid < 512) ((float*)(sm + SBIAS))[tid] = g_bias[tid];
    {
        uint4 z = make_uint4(0, 0, 0, 0);
        for (int i = tid; i < 2048; i += 512)   // zero h hi+lo (32KB)
            ((uint4*)(sm + SA_HH))[i] = z;
    }

    int erow = tid >> 3, eks = tid & 7;   // e-build: 64 rows x 8 k-slices
    auto build_e = [&](int t) {
        float2 xv = *(const float2*)&x[((size_t)(brow + erow) * Tt + t) * 2];
        #pragma unroll
        for (int cc = 0; cc < 2; cc++) {
            int kc = eks * 2 + cc;
            int k0 = kc * 8;
            uint32_t wh[4], wl[4];
            #pragma unroll
            for (int q = 0; q < 4; q++) {
                float4 sA = g_s2[t * 128 + k0 + q * 2];
                float4 sB = g_s2[t * 128 + k0 + q * 2 + 1];
                float e0 = fmaxf(fmaf(sA.x, xv.x, fmaf(sA.y, xv.y, sA.z)), 0.f);
                float e1 = fmaxf(fmaf(sB.x, xv.x, fmaf(sB.y, xv.y, sB.z)), 0.f);
                __nv_bfloat16 h0 = __float2bfloat16(e0), h1 = __float2bfloat16(e1);
                wh[q] = (uint32_t)__bfloat16_as_ushort(h0) | ((uint32_t)__bfloat16_as_ushort(h1) << 16);
                wl[q] = pkbf(e0 - __bfloat162float(h0), e1 - __bfloat162float(h1));
            }
            int off = erow * 256 + ((kc ^ (erow & 7)) << 4);
            *(uint4*)(sm + SA_EH + off) = make_uint4(wh[0], wh[1], wh[2], wh[3]);
            *(uint4*)(sm + SA_EL + off) = make_uint4(wl[0], wl[1], wl[2], wl[3]);
        }
    };
    build_e(0);
    __syncthreads();

    // issue one PAIR of panels (64KB, one commit group)
    auto issuePair = [&](int P) {
        int g0 = (2 * P) & 15;              // even; panels g0, g0+1 contiguous
        const char* src = g_wp + (size_t)g0 * 32768;
        uint32_t dst = smb + SB + ((2 * P) & 3) * 32768;   // buffers {0,1} or {2,3}
        #pragma unroll
        for (int q = 0; q < 8; q++)
            cpa16(dst + q * 8192 + tid * 16, src + q * 8192 + tid * 16);
        CP_COMMIT();
    };
    issuePair(0);

    int ar = (lane & 7) | (((lane >> 3) & 1) << 3);
    int akc = lane >> 4;
    int rx = ar & 7;
    int wn0 = w << 5;
    int bnh = (lane >> 4) & 1, bkc = (lane >> 3) & 1;
    uint32_t offB[2];
    #pragma unroll
    for (int p = 0; p < 2; p++) {
        int r = wn0 + p * 16 + bnh * 8 + (lane & 7);
        offB[p] = ((r >> 3) << 8) + (bkc << 7) + ((r & 7) << 4);
    }

    float c[4][4];
    #pragma unroll
    for (int i = 0; i < 4; i++)
        #pragma unroll
        for (int j = 0; j < 4; j++) c[i][j] = 0.f;

    for (int t = 0; t < Tt; t++) {
        float acc[4][4][4];
        #pragma unroll
        for (int i = 0; i < 4; i++)
            #pragma unroll
            for (int j = 0; j < 4; j++)
                #pragma unroll
                for (int q = 0; q < 4; q++) acc[i][j][q] = 0.f;

        for (int Pl = 0; Pl < 8; Pl++) {
            int Pg = t * 8 + Pl;
            CP_WAIT0();                 // pair Pg arrived (this thread's copies)
            __syncthreads();            // all warps done reading pair Pg-1
            if (Pg + 1 < Tt * 8) issuePair(Pg + 1);
            if (Pl == 4 && t + 1 < Tt) build_e(t + 1);   // e region dead after iter 7
            #pragma unroll
            for (int u = 0; u < 2; u++) {
                int i = Pl * 2 + u;
                uint32_t aH = smb + (i < 8 ? SA_EH : SA_HH);
                uint32_t bH = smb + SB + (((Pg * 2 + u) & 3) * 32768);
                int kc2 = (i & 7) * 2;
                uint32_t aoff = ar * 256 + (((kc2 + akc) ^ rx) << 4);
                uint32_t ah[4][4], bh[2][4];
                #pragma unroll
                for (int mf = 0; mf < 4; mf++) ldsm4(ah[mf], aH + aoff + mf * 4096);
                #pragma unroll
                for (int p = 0; p < 2; p++) ldsm4(bh[p], bH + offB[p]);
                #pragma unroll
                for (int mf = 0; mf < 4; mf++)
                    #pragma unroll
                    for (int nf = 0; nf < 4; nf++)
                        mma16816(acc[mf][nf], ah[mf], bh[nf >> 1][(nf & 1) * 2], bh[nf >> 1][(nf & 1) * 2 + 1]);
                {
                    uint32_t al[4][4];
                    #pragma unroll
                    for (int mf = 0; mf < 4; mf++) ldsm4(al[mf], aH + 16384 + aoff + mf * 4096);
                    #pragma unroll
                    for (int mf = 0; mf < 4; mf++)
                        #pragma unroll
                        for (int nf = 0; nf < 4; nf++)
                            mma16816(acc[mf][nf], al[mf], bh[nf >> 1][(nf & 1) * 2], bh[nf >> 1][(nf & 1) * 2 + 1]);
                }
                {
                    uint32_t bl[2][4];
                    #pragma unroll
                    for (int p = 0; p < 2; p++) ldsm4(bl[p], bH + 16384 + offB[p]);
                    #pragma unroll
                    for (int mf = 0; mf < 4; mf++)
                        #pragma unroll
                        for (int nf = 0; nf < 4; nf++)
                            mma16816(acc[mf][nf], ah[mf], bl[nf >> 1][(nf & 1) * 2], bl[nf >> 1][(nf & 1) * 2 + 1]);
                }
            }
        }
        __syncthreads();   // all MMA reads done; buffers {2,3} now dead -> Dst

        // ---- staged cell, 2 slabs per phase, Dst = dead ring buffers {2,3} ----
        float* Dst = (float*)(sm + SB + 65536);
        int rr = lane >> 2, cc2 = (lane & 3) << 1;
        #pragma unroll
        for (int half = 0; half < 2; half++) {
            #pragma unroll
            for (int s = 0; s < 2; s++) {
                int mf = half * 2 + s;
                #pragma unroll
                for (int nf = 0; nf < 4; nf++) {
                    int cb = wn0 + nf * 8 + cc2;
                    *(float2*)&Dst[(s * 16 + rr) * 512 + cb]       = make_float2(acc[mf][nf][0], acc[mf][nf][1]);
                    *(float2*)&Dst[(s * 16 + rr + 8) * 512 + cb]   = make_float2(acc[mf][nf][2], acc[mf][nf][3]);
                }
            }
            __syncthreads();
            #pragma unroll
            for (int s = 0; s < 2; s++) {
                int mf = half * 2 + s;
                int rowg = mf * 16 + w;
                float ya0 = 0.f, ya1 = 0.f, ya2 = 0.f, ya3 = 0.f, ya4 = 0.f;
                float hn4[4];
                int j0 = lane * 4;
                #pragma unroll
                for (int u = 0; u < 4; u++) {
                    int j = j0 + u;
                    float4 g4 = *(float4*)&Dst[(s * 16 + w) * 512 + 4 * j];
                    float4 bv = *(float4*)(sm + SBIAS + j * 16);
                    float gi = g4.x + bv.x, gf = g4.y + bv.y, gg = g4.z + bv.z, go = g4.w + bv.w;
                    float si = __fdividef(1.f, 1.f + __expf(-gi));
                    float sf = __fdividef(1.f, 1.f + __expf(-gf));
                    float tg = __fdividef(2.f, 1.f + __expf(-2.f * gg)) - 1.f;
                    float so = __fdividef(1.f, 1.f + __expf(-go));
                    float cn = sf * c[mf][u] + si * tg;
                    float tc = __fdividef(2.f, 1.f + __expf(-2.f * cn)) - 1.f;
                    float hn = so * tc;
                    c[mf][u] = cn;
                    hn4[u] = hn;
                    ya0 = fmaf(hn, swout[j * 5 + 0], ya0);
                    ya1 = fmaf(hn, swout[j * 5 + 1], ya1);
                    ya2 = fmaf(hn, swout[j * 5 + 2], ya2);
                    ya3 = fmaf(hn, swout[j * 5 + 3], ya3);
                    ya4 = fmaf(hn, swout[j * 5 + 4], ya4);
                    if (t == Tt - 1) {
                        out[OFF_H + (size_t)(brow + rowg) * 128 + j] = hn;
                        out[OFF_C + (size_t)(brow + rowg) * 128 + j] = cn;
                    }
                }
                {
                    __nv_bfloat16 h0 = __float2bfloat16(hn4[0]), h1 = __float2bfloat16(hn4[1]);
                    __nv_bfloat16 h2 = __float2bfloat16(hn4[2]), h3 = __float2bfloat16(hn4[3]);
                    uint2 wh = make_uint2(
                        (uint32_t)__bfloat16_as_ushort(h0) | ((uint32_t)__bfloat16_as_ushort(h1) << 16),
                        (uint32_t)__bfloat16_as_ushort(h2) | ((uint32_t)__bfloat16_as_ushort(h3) << 16));
                    uint2 wl2 = make_uint2(
                        pkbf(hn4[0] - __bfloat162float(h0), hn4[1] - __bfloat162float(h1)),
                        pkbf(hn4[2] - __bfloat162float(h2), hn4[3] - __bfloat162float(h3)));
                    int kc = lane >> 1;
                    int off = rowg * 256 + ((kc ^ (rowg & 7)) << 4) + (lane & 1) * 8;
                    *(uint2*)(sm + SA_HH + off) = wh;
                    *(uint2*)(sm + SA_HL + off) = wl2;
                }
                #pragma unroll
                for (int o2 = 1; o2 <= 16; o2 <<= 1) {
                    ya0 += __shfl_xor_sync(F, ya0, o2);
                    ya1 += __shfl_xor_sync(F, ya1, o2);
                    ya2 += __shfl_xor_sync(F, ya2, o2);
                    ya3 += __shfl_xor_sync(F, ya3, o2);
                    ya4 += __shfl_xor_sync(F, ya4, o2);
                }
                if (lane == 0) {
                    size_t yb = (size_t)(t * 5) * 8192 + brow + rowg;
                    g_y[yb] = ya0; g_y[yb + 8192] = ya1; g_y[yb + 16384] = ya2;
                    g_y[yb + 24576] = ya3; g_y[yb + 32768] = ya4;
                }
            }
            if (half == 0) __syncthreads();   // before restaging Dst
        }
        // new h image visible to next step's h-iterations via pair-top barriers
    }
}

__global__ void k_ystats() {
    int tf = blockIdx.x, tid = threadIdx.x;
    float s = 0.f, q = 0.f;
    for (int b = tid; b < Bsz; b += 256) {
        float v = g_y[(size_t)tf * 8192 + b];
        s += v; q += v * v;
    }
    const unsigned F = 0xffffffffu;
    #pragma unroll
    for (int o = 16; o; o >>= 1) { s += __shfl_xor_sync(F, s, o); q += __shfl_xor_sync(F, q, o); }
    __shared__ float sws[8], swq[8];
    int w = tid >> 5;
    if ((tid & 31) == 0) { sws[w] = s; swq[w] = q; }
    __syncthreads();
    if (tid == 0) {
        float S = 0.f, Q = 0.f;
        #pragma unroll
        for (int i = 0; i < 8; i++) { S += sws[i]; Q += swq[i]; }
        float mean = S * (1.0f / Bsz);
        g_ymean[tf] = mean;
        g_yrstd[tf] = rsqrtf(Q * (1.0f / Bsz) - mean * mean + 1e-5f);
    }
}
__global__ void k_ynorm(const float* __restrict__ gamma, const float* __restrict__ beta,
                        float* __restrict__ out) {
    size_t i = (size_t)blockIdx.x * 256 + threadIdx.x;
    if (i >= (size_t)Bsz * Tt * Do) return;
    size_t b = i / 640;
    int tf = (int)(i % 640);
    int f = tf % 5;
    float v = g_y[(size_t)tf * 8192 + b];
    out[i] = gamma[f] * (v - g_ymean[tf]) * g_yrstd[tf] + beta[f];
}

extern "C" void kernel_launch(void* const* d_in, const int* in_sizes, int n_in,
                              void* d_out, int out_size) {
    const float* x         = (const float*)d_in[0];
    const float* W_emb     = (const float*)d_in[1];
    const float* b_emb     = (const float*)d_in[2];
    const float* gamma_emb = (const float*)d_in[3];
    const float* beta_emb  = (const float*)d_in[4];
    const float* W_ih      = (const float*)d_in[5];
    const float* b_ih      = (const float*)d_in[6];
    const float* W_hh      = (const float*)d_in[7];
    const float* b_hh      = (const float*)d_in[8];
    const float* W_out     = (const float*)d_in[9];
    // d_in[10] = b_out: cancels exactly inside the output BatchNorm.
    const float* gamma_out = (const float*)d_in[11];
    const float* beta_out  = (const float*)d_in[12];
    float* out = (float*)d_out;

    cudaFuncSetAttribute(k_lstm, cudaFuncAttributeMaxDynamicSharedMemorySize, SMEMB);

    k_emb_stats<<<Tt, 256>>>(x, W_emb, b_emb, gamma_emb, beta_emb);  // launch 1
    k_prep<<<512, 256>>>(W_ih, W_hh, b_ih, b_hh, W_out);             // launch 2
    k_nop<<<1, 32>>>();                                              // launch 3
    k_nop<<<1, 32>>>();                                              // launch 4
    k_nop<<<1, 32>>>();                                              // launch 5
    k_lstm<<<128, 512, SMEMB>>>(x, out);                             // launch 6 <- ncu -s 5
    k_ystats<<<640, 256>>>();
    int n = Bsz * Tt * Do;
    k_ynorm<<<(n + 255) / 256, 256>>>(gamma_out, beta_out, out);
}

// round 13
// speedup vs baseline: 6.0126x; 1.2148x over previous
#include <cuda_runtime.h>
#include <cuda_bf16.h>
#include <cuda_fp16.h>
#include <math.h>
#include <stdint.h>

#define Bsz 8192
#define Tt  128
#define Do  5
#define OFF_H ((size_t)Bsz * Tt * Do)
#define OFF_C (OFF_H + (size_t)Bsz * 128)

__device__ float4 g_s2[Tt * 128];            // folded emb-BN affine (s0,s1,s2,_)
__device__ float g_bias[512];                // b_ih+b_hh permuted to n'=4j+gate
__device__ float g_woutT[640];               // W_out^T [j][f]
__device__ float g_y[(size_t)640 * Bsz];     // pre-BN y [t*5+f][row]
__device__ float g_ymean[640];
__device__ float g_yrstd[640];
// W panels: [mat(2)][kpanel(8)] x 16KB fp16; 512 n' x 16 k each
__device__ __align__(16) char g_wp[16 * 16384];

#define SA_EH 0
#define SA_EL 16384
#define SA_HH 32768
#define SA_HL 49152
#define SB    65536          // ring: 4 x 16KB = 64KB -> ends 131072
#define SDST  131072         // Dst staging 64KB -> ends 196608
#define SWOUT 196608
#define SBIAS 199168
#define SMEMB 201216

__device__ __forceinline__ uint32_t s2u(const void* p) {
    uint32_t a;
    asm("{ .reg .u64 t; cvta.to.shared.u64 t, %1; cvt.u32.u64 %0, t; }" : "=r"(a) : "l"(p));
    return a;
}
__device__ __forceinline__ void ldsm4(uint32_t r[4], uint32_t a) {
    asm volatile("ldmatrix.sync.aligned.m8n8.x4.shared.b16 {%0,%1,%2,%3}, [%4];"
        : "=r"(r[0]), "=r"(r[1]), "=r"(r[2]), "=r"(r[3]) : "r"(a));
}
__device__ __forceinline__ void mma16816(float d[4], const uint32_t a[4], uint32_t b0, uint32_t b1) {
    asm volatile("mma.sync.aligned.m16n8k16.row.col.f32.f16.f16.f32 "
        "{%0,%1,%2,%3}, {%4,%5,%6,%7}, {%8,%9}, {%0,%1,%2,%3};"
        : "+f"(d[0]), "+f"(d[1]), "+f"(d[2]), "+f"(d[3])
        : "r"(a[0]), "r"(a[1]), "r"(a[2]), "r"(a[3]), "r"(b0), "r"(b1));
}
__device__ __forceinline__ uint32_t pkhf(float a, float b) {
    __half ha = __float2half_rn(a), hb = __float2half_rn(b);
    return (uint32_t)__half_as_ushort(ha) | ((uint32_t)__half_as_ushort(hb) << 16);
}
__device__ __forceinline__ void cpa16(uint32_t dst, const void* src) {
    asm volatile("cp.async.cg.shared.global [%0], [%1], 16;" :: "r"(dst), "l"(src));
}
#define CP_COMMIT() asm volatile("cp.async.commit_group;" ::: "memory")
#define CP_WAIT0()  asm volatile("cp.async.wait_group 0;" ::: "memory")

__global__ void k_emb_stats(const float* __restrict__ x, const float* __restrict__ W_emb,
                            const float* __restrict__ b_emb, const float* __restrict__ gamma,
                            const float* __restrict__ beta) {
    int t = blockIdx.x, tid = threadIdx.x;
    float m0 = 0.f, m1 = 0.f, m00 = 0.f, m11 = 0.f, m01 = 0.f;
    for (int b = tid; b < Bsz; b += 256) {
        size_t xi = ((size_t)b * Tt + t) * 2;
        float x0 = x[xi], x1 = x[xi + 1];
        m0 += x0; m1 += x1; m00 += x0 * x0; m11 += x1 * x1; m01 += x0 * x1;
    }
    const unsigned F = 0xffffffffu;
    #pragma unroll
    for (int o = 16; o; o >>= 1) {
        m0 += __shfl_xor_sync(F, m0, o); m1 += __shfl_xor_sync(F, m1, o);
        m00 += __shfl_xor_sync(F, m00, o); m11 += __shfl_xor_sync(F, m11, o);
        m01 += __shfl_xor_sync(F, m01, o);
    }
    __shared__ float sw[8][5], mom[5];
    int w = tid >> 5, l = tid & 31;
    if (l == 0) { sw[w][0] = m0; sw[w][1] = m1; sw[w][2] = m00; sw[w][3] = m11; sw[w][4] = m01; }
    __syncthreads();
    if (tid < 5) {
        float s = 0.f;
        #pragma unroll
        for (int i = 0; i < 8; i++) s += sw[i][tid];
        mom[tid] = s * (1.0f / Bsz);
    }
    __syncthreads();
    if (tid < 128) {
        float mx0 = mom[0], mx1 = mom[1];
        float vx0 = mom[2] - mx0 * mx0, vx1 = mom[3] - mx1 * mx1, cxy = mom[4] - mx0 * mx1;
        float w0 = W_emb[tid * 2], w1 = W_emb[tid * 2 + 1];
        float mu = w0 * mx0 + w1 * mx1 + b_emb[tid];
        float var = w0 * w0 * vx0 + 2.0f * w0 * w1 * cxy + w1 * w1 * vx1;
        float gr = gamma[tid] * rsqrtf(var + 1e-5f);
        g_s2[t * 128 + tid] = make_float4(gr * w0, gr * w1,
                                          gr * (b_emb[tid] - mu) + beta[tid], 0.f);
    }
}

__global__ void k_prep(const float* __restrict__ Wih, const float* __restrict__ Whh,
                       const float* __restrict__ bih, const float* __restrict__ bhh,
                       const float* __restrict__ Wout) {
    int id = blockIdx.x * 256 + threadIdx.x;  // 131072
    int mat = id >> 16, e = id & 65535;
    int np = e >> 7, k = e & 127;
    int src = ((np & 3) * 128 + (np >> 2)) * 128 + k;
    float wv = mat ? Whh[src] : Wih[src];
    int kl = k & 15;
    int off = (mat * 8 + (k >> 4)) * 16384
            + ((np >> 3) << 8) + ((kl >> 3) << 7) + ((np & 7) << 4) + ((kl & 7) << 1);
    *(__half*)(g_wp + off) = __float2half_rn(wv);
    if (id < 512) {
        int orig = (id & 3) * 128 + (id >> 2);
        g_bias[id] = bih[orig] + bhh[orig];
    }
    if (id >= 1024 && id < 1664) {
        int idx = id - 1024;
        g_woutT[(idx & 127) * 5 + (idx >> 7)] = Wout[idx];
    }
}

__global__ void k_nop() {}

// persistent recurrence: block = 64 rows x 512 gates, 16 warps (warp tile 64x32)
// fp16 2-pass: gates = (A_hi + A_lo) @ B_fp16
__global__ void __launch_bounds__(512, 1) k_lstm(const float* __restrict__ x,
                                                 float* __restrict__ out) {
    extern __shared__ char sm[];
    uint32_t smb = s2u(sm);
    float* swout = (float*)(sm + SWOUT);
    int tid = threadIdx.x, lane = tid & 31, w = tid >> 5;   // w in 0..15
    int brow = blockIdx.x << 6;
    const unsigned F = 0xffffffffu;

    for (int i = tid; i < 640; i += 512) swout[i] = g_woutT[i];
    if (tid < 512) ((float*)(sm + SBIAS))[tid] = g_bias[tid];
    {
        uint4 z = make_uint4(0, 0, 0, 0);
        for (int i = tid; i < 2048; i += 512)   // zero h hi+lo (32KB)
            ((uint4*)(sm + SA_HH))[i] = z;
    }

    int erow = tid >> 3, eks = tid & 7;   // e-build: 64 rows x 8 k-slices
    auto build_e = [&](int t) {
        float2 xv = *(const float2*)&x[((size_t)(brow + erow) * Tt + t) * 2];
        #pragma unroll
        for (int cc = 0; cc < 2; cc++) {
            int kc = eks * 2 + cc;
            int k0 = kc * 8;
            uint32_t wh[4], wl[4];
            #pragma unroll
            for (int q = 0; q < 4; q++) {
                float4 sA = g_s2[t * 128 + k0 + q * 2];
                float4 sB = g_s2[t * 128 + k0 + q * 2 + 1];
                float e0 = fmaxf(fmaf(sA.x, xv.x, fmaf(sA.y, xv.y, sA.z)), 0.f);
                float e1 = fmaxf(fmaf(sB.x, xv.x, fmaf(sB.y, xv.y, sB.z)), 0.f);
                __half h0 = __float2half_rn(e0), h1 = __float2half_rn(e1);
                wh[q] = (uint32_t)__half_as_ushort(h0) | ((uint32_t)__half_as_ushort(h1) << 16);
                wl[q] = pkhf(e0 - __half2float(h0), e1 - __half2float(h1));
            }
            int off = erow * 256 + ((kc ^ (erow & 7)) << 4);
            *(uint4*)(sm + SA_EH + off) = make_uint4(wh[0], wh[1], wh[2], wh[3]);
            *(uint4*)(sm + SA_EL + off) = make_uint4(wl[0], wl[1], wl[2], wl[3]);
        }
    };
    build_e(0);
    __syncthreads();

    // issue one PAIR of fp16 panels (32KB, one commit group)
    auto issuePair = [&](int P) {
        int g0 = (2 * P) & 15;              // even; panels g0, g0+1 contiguous
        const char* src = g_wp + (size_t)g0 * 16384;
        uint32_t dst = smb + SB + ((2 * P) & 3) * 16384;   // buffers {0,1} or {2,3}
        #pragma unroll
        for (int q = 0; q < 4; q++)
            cpa16(dst + q * 8192 + tid * 16, src + q * 8192 + tid * 16);
        CP_COMMIT();
    };
    issuePair(0);

    int ar = (lane & 7) | (((lane >> 3) & 1) << 3);
    int akc = lane >> 4;
    int rx = ar & 7;
    int wn0 = w << 5;
    int bnh = (lane >> 4) & 1, bkc = (lane >> 3) & 1;
    uint32_t offB[2];
    #pragma unroll
    for (int p = 0; p < 2; p++) {
        int r = wn0 + p * 16 + bnh * 8 + (lane & 7);
        offB[p] = ((r >> 3) << 8) + (bkc << 7) + ((r & 7) << 4);
    }

    float c[4][4];
    #pragma unroll
    for (int i = 0; i < 4; i++)
        #pragma unroll
        for (int j = 0; j < 4; j++) c[i][j] = 0.f;

    for (int t = 0; t < Tt; t++) {
        float acc[4][4][4];
        #pragma unroll
        for (int i = 0; i < 4; i++)
            #pragma unroll
            for (int j = 0; j < 4; j++)
                #pragma unroll
                for (int q = 0; q < 4; q++) acc[i][j][q] = 0.f;

        for (int Pl = 0; Pl < 8; Pl++) {
            int Pg = t * 8 + Pl;
            CP_WAIT0();                 // pair Pg arrived
            __syncthreads();            // all warps done reading pair Pg-1
            if (Pg + 1 < Tt * 8) issuePair(Pg + 1);
            if (Pl == 4 && t + 1 < Tt) build_e(t + 1);   // e region dead after iter 7
            #pragma unroll
            for (int u = 0; u < 2; u++) {
                int i = Pl * 2 + u;
                uint32_t aH = smb + (i < 8 ? SA_EH : SA_HH);
                uint32_t bH = smb + SB + (((Pg * 2 + u) & 3) * 16384);
                int kc2 = (i & 7) * 2;
                uint32_t aoff = ar * 256 + (((kc2 + akc) ^ rx) << 4);
                uint32_t ah[4][4], bh[2][4];
                #pragma unroll
                for (int mf = 0; mf < 4; mf++) ldsm4(ah[mf], aH + aoff + mf * 4096);
                #pragma unroll
                for (int p = 0; p < 2; p++) ldsm4(bh[p], bH + offB[p]);
                #pragma unroll
                for (int mf = 0; mf < 4; mf++)
                    #pragma unroll
                    for (int nf = 0; nf < 4; nf++)
                        mma16816(acc[mf][nf], ah[mf], bh[nf >> 1][(nf & 1) * 2], bh[nf >> 1][(nf & 1) * 2 + 1]);
                {
                    uint32_t al[4][4];
                    #pragma unroll
                    for (int mf = 0; mf < 4; mf++) ldsm4(al[mf], aH + 16384 + aoff + mf * 4096);
                    #pragma unroll
                    for (int mf = 0; mf < 4; mf++)
                        #pragma unroll
                        for (int nf = 0; nf < 4; nf++)
                            mma16816(acc[mf][nf], al[mf], bh[nf >> 1][(nf & 1) * 2], bh[nf >> 1][(nf & 1) * 2 + 1]);
                }
            }
        }
        __syncthreads();   // all MMA + prior cell reads done -> stage

        // ---- staged cell, 2 slabs per phase, dedicated Dst region ----
        float* Dst = (float*)(sm + SDST);
        int rr = lane >> 2, cc2 = (lane & 3) << 1;
        #pragma unroll
        for (int half = 0; half < 2; half++) {
            #pragma unroll
            for (int s = 0; s < 2; s++) {
                int mf = half * 2 + s;
                #pragma unroll
                for (int nf = 0; nf < 4; nf++) {
                    int cb = wn0 + nf * 8 + cc2;
                    *(float2*)&Dst[(s * 16 + rr) * 512 + cb]     = make_float2(acc[mf][nf][0], acc[mf][nf][1]);
                    *(float2*)&Dst[(s * 16 + rr + 8) * 512 + cb] = make_float2(acc[mf][nf][2], acc[mf][nf][3]);
                }
            }
            __syncthreads();
            #pragma unroll
            for (int s = 0; s < 2; s++) {
                int mf = half * 2 + s;
                int rowg = mf * 16 + w;
                float ya0 = 0.f, ya1 = 0.f, ya2 = 0.f, ya3 = 0.f, ya4 = 0.f;
                float hn4[4];
                int j0 = lane * 4;
                #pragma unroll
                for (int u = 0; u < 4; u++) {
                    int j = j0 + u;
                    float4 g4 = *(float4*)&Dst[(s * 16 + w) * 512 + 4 * j];
                    float4 bv = *(float4*)(sm + SBIAS + j * 16);
                    float gi = g4.x + bv.x, gf = g4.y + bv.y, gg = g4.z + bv.z, go = g4.w + bv.w;
                    float si = __fdividef(1.f, 1.f + __expf(-gi));
                    float sf = __fdividef(1.f, 1.f + __expf(-gf));
                    float tg = __fdividef(2.f, 1.f + __expf(-2.f * gg)) - 1.f;
                    float so = __fdividef(1.f, 1.f + __expf(-go));
                    float cn = sf * c[mf][u] + si * tg;
                    float tc = __fdividef(2.f, 1.f + __expf(-2.f * cn)) - 1.f;
                    float hn = so * tc;
                    c[mf][u] = cn;
                    hn4[u] = hn;
                    ya0 = fmaf(hn, swout[j * 5 + 0], ya0);
                    ya1 = fmaf(hn, swout[j * 5 + 1], ya1);
                    ya2 = fmaf(hn, swout[j * 5 + 2], ya2);
                    ya3 = fmaf(hn, swout[j * 5 + 3], ya3);
                    ya4 = fmaf(hn, swout[j * 5 + 4], ya4);
                    if (t == Tt - 1) {
                        out[OFF_H + (size_t)(brow + rowg) * 128 + j] = hn;
                        out[OFF_C + (size_t)(brow + rowg) * 128 + j] = cn;
                    }
                }
                {
                    __half h0 = __float2half_rn(hn4[0]), h1 = __float2half_rn(hn4[1]);
                    __half h2 = __float2half_rn(hn4[2]), h3 = __float2half_rn(hn4[3]);
                    uint2 wh = make_uint2(
                        (uint32_t)__half_as_ushort(h0) | ((uint32_t)__half_as_ushort(h1) << 16),
                        (uint32_t)__half_as_ushort(h2) | ((uint32_t)__half_as_ushort(h3) << 16));
                    uint2 wl2 = make_uint2(
                        pkhf(hn4[0] - __half2float(h0), hn4[1] - __half2float(h1)),
                        pkhf(hn4[2] - __half2float(h2), hn4[3] - __half2float(h3)));
                    int kc = lane >> 1;
                    int off = rowg * 256 + ((kc ^ (rowg & 7)) << 4) + (lane & 1) * 8;
                    *(uint2*)(sm + SA_HH + off) = wh;
                    *(uint2*)(sm + SA_HL + off) = wl2;
                }
                #pragma unroll
                for (int o2 = 1; o2 <= 16; o2 <<= 1) {
                    ya0 += __shfl_xor_sync(F, ya0, o2);
                    ya1 += __shfl_xor_sync(F, ya1, o2);
                    ya2 += __shfl_xor_sync(F, ya2, o2);
                    ya3 += __shfl_xor_sync(F, ya3, o2);
                    ya4 += __shfl_xor_sync(F, ya4, o2);
                }
                if (lane == 0) {
                    size_t yb = (size_t)(t * 5) * 8192 + brow + rowg;
                    g_y[yb] = ya0; g_y[yb + 8192] = ya1; g_y[yb + 16384] = ya2;
                    g_y[yb + 24576] = ya3; g_y[yb + 32768] = ya4;
                }
            }
            if (half == 0) __syncthreads();   // before restaging Dst
        }
        // new h image visible to next step's h-iterations via pair-top barriers
    }
}

__global__ void k_ystats() {
    int tf = blockIdx.x, tid = threadIdx.x;
    float s = 0.f, q = 0.f;
    for (int b = tid; b < Bsz; b += 256) {
        float v = g_y[(size_t)tf * 8192 + b];
        s += v; q += v * v;
    }
    const unsigned F = 0xffffffffu;
    #pragma unroll
    for (int o = 16; o; o >>= 1) { s += __shfl_xor_sync(F, s, o); q += __shfl_xor_sync(F, q, o); }
    __shared__ float sws[8], swq[8];
    int w = tid >> 5;
    if ((tid & 31) == 0) { sws[w] = s; swq[w] = q; }
    __syncthreads();
    if (tid == 0) {
        float S = 0.f, Q = 0.f;
        #pragma unroll
        for (int i = 0; i < 8; i++) { S += sws[i]; Q += swq[i]; }
        float mean = S * (1.0f / Bsz);
        g_ymean[tf] = mean;
        g_yrstd[tf] = rsqrtf(Q * (1.0f / Bsz) - mean * mean + 1e-5f);
    }
}
__global__ void k_ynorm(const float* __restrict__ gamma, const float* __restrict__ beta,
                        float* __restrict__ out) {
    size_t i = (size_t)blockIdx.x * 256 + threadIdx.x;
    if (i >= (size_t)Bsz * Tt * Do) return;
    size_t b = i / 640;
    int tf = (int)(i % 640);
    int f = tf % 5;
    float v = g_y[(size_t)tf * 8192 + b];
    out[i] = gamma[f] * (v - g_ymean[tf]) * g_yrstd[tf] + beta[f];
}

extern "C" void kernel_launch(void* const* d_in, const int* in_sizes, int n_in,
                              void* d_out, int out_size) {
    const float* x         = (const float*)d_in[0];
    const float* W_emb     = (const float*)d_in[1];
    const float* b_emb     = (const float*)d_in[2];
    const float* gamma_emb = (const float*)d_in[3];
    const float* beta_emb  = (const float*)d_in[4];
    const float* W_ih      = (const float*)d_in[5];
    const float* b_ih      = (const float*)d_in[6];
    const float* W_hh      = (const float*)d_in[7];
    const float* b_hh      = (const float*)d_in[8];
    const float* W_out     = (const float*)d_in[9];
    // d_in[10] = b_out: cancels exactly inside the output BatchNorm.
    const float* gamma_out = (const float*)d_in[11];
    const float* beta_out  = (const float*)d_in[12];
    float* out = (float*)d_out;

    cudaFuncSetAttribute(k_lstm, cudaFuncAttributeMaxDynamicSharedMemorySize, SMEMB);

    k_emb_stats<<<Tt, 256>>>(x, W_emb, b_emb, gamma_emb, beta_emb);  // launch 1
    k_prep<<<512, 256>>>(W_ih, W_hh, b_ih, b_hh, W_out);             // launch 2
    k_nop<<<1, 32>>>();                                              // launch 3
    k_nop<<<1, 32>>>();                                              // launch 4
    k_lstm<<<128, 512, SMEMB>>>(x, out);                             // launch 5 <- ncu
    k_ystats<<<640, 256>>>();
    int n = Bsz * Tt * Do;
    k_ynorm<<<(n + 255) / 256, 256>>>(gamma_out, beta_out, out);
}

// round 14
// speedup vs baseline: 6.0363x; 1.0039x over previous
#include <cuda_runtime.h>
#include <cuda_bf16.h>
#include <cuda_fp16.h>
#include <math.h>
#include <stdint.h>

#define Bsz 8192
#define Tt  128
#define Do  5
#define OFF_H ((size_t)Bsz * Tt * Do)
#define OFF_C (OFF_H + (size_t)Bsz * 128)

__device__ float4 g_s2[Tt * 128];            // folded emb-BN affine (s0,s1,s2,_)
__device__ float g_bias[512];                // b_ih+b_hh permuted to n'=4j+gate
__device__ float g_woutT[640];               // W_out^T [j][f]
__device__ float g_y[(size_t)640 * Bsz];     // pre-BN y [t*5+f][row]
__device__ float g_ymean[640];
__device__ float g_yrstd[640];
// W panels: [mat(2)][kpanel(8)] x 16KB fp16; 512 n' x 16 k each
__device__ __align__(16) char g_wp[16 * 16384];

#define SA_EH 0
#define SA_EL 16384
#define SA_HH 32768
#define SA_HL 49152
#define SB    65536          // ring: 4 x 16KB = 64KB -> ends 131072
#define SDST  131072         // Dst staging 64KB -> ends 196608
#define SWOUT 196608
#define SBIAS 199168
#define SMEMB 201216

__device__ __forceinline__ uint32_t s2u(const void* p) {
    uint32_t a;
    asm("{ .reg .u64 t; cvta.to.shared.u64 t, %1; cvt.u32.u64 %0, t; }" : "=r"(a) : "l"(p));
    return a;
}
__device__ __forceinline__ void ldsm4(uint32_t r[4], uint32_t a) {
    asm volatile("ldmatrix.sync.aligned.m8n8.x4.shared.b16 {%0,%1,%2,%3}, [%4];"
        : "=r"(r[0]), "=r"(r[1]), "=r"(r[2]), "=r"(r[3]) : "r"(a));
}
__device__ __forceinline__ void mma16816(float d[4], const uint32_t a[4], uint32_t b0, uint32_t b1) {
    asm volatile("mma.sync.aligned.m16n8k16.row.col.f32.f16.f16.f32 "
        "{%0,%1,%2,%3}, {%4,%5,%6,%7}, {%8,%9}, {%0,%1,%2,%3};"
        : "+f"(d[0]), "+f"(d[1]), "+f"(d[2]), "+f"(d[3])
        : "r"(a[0]), "r"(a[1]), "r"(a[2]), "r"(a[3]), "r"(b0), "r"(b1));
}
__device__ __forceinline__ uint32_t pkhf(float a, float b) {
    __half ha = __float2half_rn(a), hb = __float2half_rn(b);
    return (uint32_t)__half_as_ushort(ha) | ((uint32_t)__half_as_ushort(hb) << 16);
}
__device__ __forceinline__ void cpa16(uint32_t dst, const void* src) {
    asm volatile("cp.async.cg.shared.global [%0], [%1], 16;" :: "r"(dst), "l"(src));
}
#define CP_COMMIT() asm volatile("cp.async.commit_group;" ::: "memory")
#define CP_WAIT0()  asm volatile("cp.async.wait_group 0;" ::: "memory")

__global__ void k_emb_stats(const float* __restrict__ x, const float* __restrict__ W_emb,
                            const float* __restrict__ b_emb, const float* __restrict__ gamma,
                            const float* __restrict__ beta) {
    int t = blockIdx.x, tid = threadIdx.x;
    float m0 = 0.f, m1 = 0.f, m00 = 0.f, m11 = 0.f, m01 = 0.f;
    for (int b = tid; b < Bsz; b += 256) {
        size_t xi = ((size_t)b * Tt + t) * 2;
        float x0 = x[xi], x1 = x[xi + 1];
        m0 += x0; m1 += x1; m00 += x0 * x0; m11 += x1 * x1; m01 += x0 * x1;
    }
    const unsigned F = 0xffffffffu;
    #pragma unroll
    for (int o = 16; o; o >>= 1) {
        m0 += __shfl_xor_sync(F, m0, o); m1 += __shfl_xor_sync(F, m1, o);
        m00 += __shfl_xor_sync(F, m00, o); m11 += __shfl_xor_sync(F, m11, o);
        m01 += __shfl_xor_sync(F, m01, o);
    }
    __shared__ float sw[8][5], mom[5];
    int w = tid >> 5, l = tid & 31;
    if (l == 0) { sw[w][0] = m0; sw[w][1] = m1; sw[w][2] = m00; sw[w][3] = m11; sw[w][4] = m01; }
    __syncthreads();
    if (tid < 5) {
        float s = 0.f;
        #pragma unroll
        for (int i = 0; i < 8; i++) s += sw[i][tid];
        mom[tid] = s * (1.0f / Bsz);
    }
    __syncthreads();
    if (tid < 128) {
        float mx0 = mom[0], mx1 = mom[1];
        float vx0 = mom[2] - mx0 * mx0, vx1 = mom[3] - mx1 * mx1, cxy = mom[4] - mx0 * mx1;
        float w0 = W_emb[tid * 2], w1 = W_emb[tid * 2 + 1];
        float mu = w0 * mx0 + w1 * mx1 + b_emb[tid];
        float var = w0 * w0 * vx0 + 2.0f * w0 * w1 * cxy + w1 * w1 * vx1;
        float gr = gamma[tid] * rsqrtf(var + 1e-5f);
        g_s2[t * 128 + tid] = make_float4(gr * w0, gr * w1,
                                          gr * (b_emb[tid] - mu) + beta[tid], 0.f);
    }
}

__global__ void k_prep(const float* __restrict__ Wih, const float* __restrict__ Whh,
                       const float* __restrict__ bih, const float* __restrict__ bhh,
                       const float* __restrict__ Wout) {
    int id = blockIdx.x * 256 + threadIdx.x;  // 131072
    int mat = id >> 16, e = id & 65535;
    int np = e >> 7, k = e & 127;
    int src = ((np & 3) * 128 + (np >> 2)) * 128 + k;
    float wv = mat ? Whh[src] : Wih[src];
    int kl = k & 15;
    int off = (mat * 8 + (k >> 4)) * 16384
            + ((np >> 3) << 8) + ((kl >> 3) << 7) + ((np & 7) << 4) + ((kl & 7) << 1);
    *(__half*)(g_wp + off) = __float2half_rn(wv);
    if (id < 512) {
        int orig = (id & 3) * 128 + (id >> 2);
        g_bias[id] = bih[orig] + bhh[orig];
    }
    if (id >= 1024 && id < 1664) {
        int idx = id - 1024;
        g_woutT[(idx & 127) * 5 + (idx >> 7)] = Wout[idx];
    }
}

__global__ void k_nop() {}

// persistent recurrence: block = 64 rows x 512 gates, 16 warps (warp tile 64x32)
// fp16 2-pass: gates = (A_hi + A_lo) @ B_fp16
__global__ void __launch_bounds__(512, 1) k_lstm(const float* __restrict__ x,
                                                 float* __restrict__ out) {
    extern __shared__ char sm[];
    uint32_t smb = s2u(sm);
    float* swout = (float*)(sm + SWOUT);
    int tid = threadIdx.x, lane = tid & 31, w = tid >> 5;   // w in 0..15
    int brow = blockIdx.x << 6;
    const unsigned F = 0xffffffffu;

    for (int i = tid; i < 640; i += 512) swout[i] = g_woutT[i];
    if (tid < 512) ((float*)(sm + SBIAS))[tid] = g_bias[tid];
    {
        uint4 z = make_uint4(0, 0, 0, 0);
        for (int i = tid; i < 2048; i += 512)   // zero h hi+lo (32KB)
            ((uint4*)(sm + SA_HH))[i] = z;
    }

    int erow = tid >> 3, eks = tid & 7;   // e-build: 64 rows x 8 k-slices
    auto build_e = [&](int t) {
        float2 xv = *(const float2*)&x[((size_t)(brow + erow) * Tt + t) * 2];
        #pragma unroll
        for (int cc = 0; cc < 2; cc++) {
            int kc = eks * 2 + cc;
            int k0 = kc * 8;
            uint32_t wh[4], wl[4];
            #pragma unroll
            for (int q = 0; q < 4; q++) {
                float4 sA = g_s2[t * 128 + k0 + q * 2];
                float4 sB = g_s2[t * 128 + k0 + q * 2 + 1];
                float e0 = fmaxf(fmaf(sA.x, xv.x, fmaf(sA.y, xv.y, sA.z)), 0.f);
                float e1 = fmaxf(fmaf(sB.x, xv.x, fmaf(sB.y, xv.y, sB.z)), 0.f);
                __half h0 = __float2half_rn(e0), h1 = __float2half_rn(e1);
                wh[q] = (uint32_t)__half_as_ushort(h0) | ((uint32_t)__half_as_ushort(h1) << 16);
                wl[q] = pkhf(e0 - __half2float(h0), e1 - __half2float(h1));
            }
            int off = erow * 256 + ((kc ^ (erow & 7)) << 4);
            *(uint4*)(sm + SA_EH + off) = make_uint4(wh[0], wh[1], wh[2], wh[3]);
            *(uint4*)(sm + SA_EL + off) = make_uint4(wl[0], wl[1], wl[2], wl[3]);
        }
    };
    build_e(0);
    __syncthreads();

    // issue one PAIR of fp16 panels (32KB, one commit group)
    auto issuePair = [&](int P) {
        int g0 = (2 * P) & 15;              // even; panels g0, g0+1 contiguous
        const char* src = g_wp + (size_t)g0 * 16384;
        uint32_t dst = smb + SB + ((2 * P) & 3) * 16384;   // buffers {0,1} or {2,3}
        #pragma unroll
        for (int q = 0; q < 4; q++)
            cpa16(dst + q * 8192 + tid * 16, src + q * 8192 + tid * 16);
        CP_COMMIT();
    };
    issuePair(0);

    int ar = (lane & 7) | (((lane >> 3) & 1) << 3);
    int akc = lane >> 4;
    int rx = ar & 7;
    int wn0 = w << 5;
    int bnh = (lane >> 4) & 1, bkc = (lane >> 3) & 1;
    uint32_t offB[2];
    #pragma unroll
    for (int p = 0; p < 2; p++) {
        int r = wn0 + p * 16 + bnh * 8 + (lane & 7);
        offB[p] = ((r >> 3) << 8) + (bkc << 7) + ((r & 7) << 4);
    }

    float c[4][4];
    #pragma unroll
    for (int i = 0; i < 4; i++)
        #pragma unroll
        for (int j = 0; j < 4; j++) c[i][j] = 0.f;

    for (int t = 0; t < Tt; t++) {
        float acc[4][4][4];
        #pragma unroll
        for (int i = 0; i < 4; i++)
            #pragma unroll
            for (int j = 0; j < 4; j++)
                #pragma unroll
                for (int q = 0; q < 4; q++) acc[i][j][q] = 0.f;

        for (int Pl = 0; Pl < 8; Pl++) {
            int Pg = t * 8 + Pl;
            CP_WAIT0();                 // pair Pg arrived
            __syncthreads();            // all warps done reading pair Pg-1
            if (Pg + 1 < Tt * 8) issuePair(Pg + 1);
            if (Pl == 4 && t + 1 < Tt) build_e(t + 1);   // e region dead after iter 7
            #pragma unroll
            for (int u = 0; u < 2; u++) {
                int i = Pl * 2 + u;
                uint32_t aH = smb + (i < 8 ? SA_EH : SA_HH);
                uint32_t bH = smb + SB + (((Pg * 2 + u) & 3) * 16384);
                int kc2 = (i & 7) * 2;
                uint32_t aoff = ar * 256 + (((kc2 + akc) ^ rx) << 4);
                uint32_t ah[4][4], bh[2][4];
                #pragma unroll
                for (int mf = 0; mf < 4; mf++) ldsm4(ah[mf], aH + aoff + mf * 4096);
                #pragma unroll
                for (int p = 0; p < 2; p++) ldsm4(bh[p], bH + offB[p]);
                #pragma unroll
                for (int mf = 0; mf < 4; mf++)
                    #pragma unroll
                    for (int nf = 0; nf < 4; nf++)
                        mma16816(acc[mf][nf], ah[mf], bh[nf >> 1][(nf & 1) * 2], bh[nf >> 1][(nf & 1) * 2 + 1]);
                {
                    uint32_t al[4][4];
                    #pragma unroll
                    for (int mf = 0; mf < 4; mf++) ldsm4(al[mf], aH + 16384 + aoff + mf * 4096);
                    #pragma unroll
                    for (int mf = 0; mf < 4; mf++)
                        #pragma unroll
                        for (int nf = 0; nf < 4; nf++)
                            mma16816(acc[mf][nf], al[mf], bh[nf >> 1][(nf & 1) * 2], bh[nf >> 1][(nf & 1) * 2 + 1]);
                }
            }
        }
        __syncthreads();   // all MMA + prior cell reads done -> stage

        // ---- staged cell, 2 slabs per phase, dedicated Dst region ----
        float* Dst = (float*)(sm + SDST);
        int rr = lane >> 2, cc2 = (lane & 3) << 1;
        #pragma unroll
        for (int half = 0; half < 2; half++) {
            #pragma unroll
            for (int s = 0; s < 2; s++) {
                int mf = half * 2 + s;
                #pragma unroll
                for (int nf = 0; nf < 4; nf++) {
                    int cb = wn0 + nf * 8 + cc2;
                    *(float2*)&Dst[(s * 16 + rr) * 512 + cb]     = make_float2(acc[mf][nf][0], acc[mf][nf][1]);
                    *(float2*)&Dst[(s * 16 + rr + 8) * 512 + cb] = make_float2(acc[mf][nf][2], acc[mf][nf][3]);
                }
            }
            __syncthreads();
            #pragma unroll
            for (int s = 0; s < 2; s++) {
                int mf = half * 2 + s;
                int rowg = mf * 16 + w;
                float ya0 = 0.f, ya1 = 0.f, ya2 = 0.f, ya3 = 0.f, ya4 = 0.f;
                float hn4[4];
                int j0 = lane * 4;
                #pragma unroll
                for (int u = 0; u < 4; u++) {
                    int j = j0 + u;
                    float4 g4 = *(float4*)&Dst[(s * 16 + w) * 512 + 4 * j];
                    float4 bv = *(float4*)(sm + SBIAS + j * 16);
                    float gi = g4.x + bv.x, gf = g4.y + bv.y, gg = g4.z + bv.z, go = g4.w + bv.w;
                    float si = __fdividef(1.f, 1.f + __expf(-gi));
                    float sf = __fdividef(1.f, 1.f + __expf(-gf));
                    float tg = __fdividef(2.f, 1.f + __expf(-2.f * gg)) - 1.f;
                    float so = __fdividef(1.f, 1.f + __expf(-go));
                    float cn = sf * c[mf][u] + si * tg;
                    float tc = __fdividef(2.f, 1.f + __expf(-2.f * cn)) - 1.f;
                    float hn = so * tc;
                    c[mf][u] = cn;
                    hn4[u] = hn;
                    ya0 = fmaf(hn, swout[j * 5 + 0], ya0);
                    ya1 = fmaf(hn, swout[j * 5 + 1], ya1);
                    ya2 = fmaf(hn, swout[j * 5 + 2], ya2);
                    ya3 = fmaf(hn, swout[j * 5 + 3], ya3);
                    ya4 = fmaf(hn, swout[j * 5 + 4], ya4);
                    if (t == Tt - 1) {
                        out[OFF_H + (size_t)(brow + rowg) * 128 + j] = hn;
                        out[OFF_C + (size_t)(brow + rowg) * 128 + j] = cn;
                    }
                }
                {
                    __half h0 = __float2half_rn(hn4[0]), h1 = __float2half_rn(hn4[1]);
                    __half h2 = __float2half_rn(hn4[2]), h3 = __float2half_rn(hn4[3]);
                    uint2 wh = make_uint2(
                        (uint32_t)__half_as_ushort(h0) | ((uint32_t)__half_as_ushort(h1) << 16),
                        (uint32_t)__half_as_ushort(h2) | ((uint32_t)__half_as_ushort(h3) << 16));
                    uint2 wl2 = make_uint2(
                        pkhf(hn4[0] - __half2float(h0), hn4[1] - __half2float(h1)),
                        pkhf(hn4[2] - __half2float(h2), hn4[3] - __half2float(h3)));
                    int kc = lane >> 1;
                    int off = rowg * 256 + ((kc ^ (rowg & 7)) << 4) + (lane & 1) * 8;
                    *(uint2*)(sm + SA_HH + off) = wh;
                    *(uint2*)(sm + SA_HL + off) = wl2;
                }
                #pragma unroll
                for (int o2 = 1; o2 <= 16; o2 <<= 1) {
                    ya0 += __shfl_xor_sync(F, ya0, o2);
                    ya1 += __shfl_xor_sync(F, ya1, o2);
                    ya2 += __shfl_xor_sync(F, ya2, o2);
                    ya3 += __shfl_xor_sync(F, ya3, o2);
                    ya4 += __shfl_xor_sync(F, ya4, o2);
                }
                if (lane == 0) {
                    size_t yb = (size_t)(t * 5) * 8192 + brow + rowg;
                    g_y[yb] = ya0; g_y[yb + 8192] = ya1; g_y[yb + 16384] = ya2;
                    g_y[yb + 24576] = ya3; g_y[yb + 32768] = ya4;
                }
            }
            if (half == 0) __syncthreads();   // before restaging Dst
        }
        // new h image visible to next step's h-iterations via pair-top barriers
    }
}

__global__ void k_ystats() {
    int tf = blockIdx.x, tid = threadIdx.x;
    float s = 0.f, q = 0.f;
    for (int b = tid; b < Bsz; b += 256) {
        float v = g_y[(size_t)tf * 8192 + b];
        s += v; q += v * v;
    }
    const unsigned F = 0xffffffffu;
    #pragma unroll
    for (int o = 16; o; o >>= 1) { s += __shfl_xor_sync(F, s, o); q += __shfl_xor_sync(F, q, o); }
    __shared__ float sws[8], swq[8];
    int w = tid >> 5;
    if ((tid & 31) == 0) { sws[w] = s; swq[w] = q; }
    __syncthreads();
    if (tid == 0) {
        float S = 0.f, Q = 0.f;
        #pragma unroll
        for (int i = 0; i < 8; i++) { S += sws[i]; Q += swq[i]; }
        float mean = S * (1.0f / Bsz);
        g_ymean[tf] = mean;
        g_yrstd[tf] = rsqrtf(Q * (1.0f / Bsz) - mean * mean + 1e-5f);
    }
}
__global__ void k_ynorm(const float* __restrict__ gamma, const float* __restrict__ beta,
                        float* __restrict__ out) {
    size_t i = (size_t)blockIdx.x * 256 + threadIdx.x;
    if (i >= (size_t)Bsz * Tt * Do) return;
    size_t b = i / 640;
    int tf = (int)(i % 640);
    int f = tf % 5;
    float v = g_y[(size_t)tf * 8192 + b];
    out[i] = gamma[f] * (v - g_ymean[tf]) * g_yrstd[tf] + beta[f];
}

extern "C" void kernel_launch(void* const* d_in, const int* in_sizes, int n_in,
                              void* d_out, int out_size) {
    const float* x         = (const float*)d_in[0];
    const float* W_emb     = (const float*)d_in[1];
    const float* b_emb     = (const float*)d_in[2];
    const float* gamma_emb = (const float*)d_in[3];
    const float* beta_emb  = (const float*)d_in[4];
    const float* W_ih      = (const float*)d_in[5];
    const float* b_ih      = (const float*)d_in[6];
    const float* W_hh      = (const float*)d_in[7];
    const float* b_hh      = (const float*)d_in[8];
    const float* W_out     = (const float*)d_in[9];
    // d_in[10] = b_out: cancels exactly inside the output BatchNorm.
    const float* gamma_out = (const float*)d_in[11];
    const float* beta_out  = (const float*)d_in[12];
    float* out = (float*)d_out;

    cudaFuncSetAttribute(k_lstm, cudaFuncAttributeMaxDynamicSharedMemorySize, SMEMB);

    k_emb_stats<<<Tt, 256>>>(x, W_emb, b_emb, gamma_emb, beta_emb);  // launch 1
    k_prep<<<512, 256>>>(W_ih, W_hh, b_ih, b_hh, W_out);             // launch 2
    k_nop<<<1, 32>>>();                                              // launch 3
    k_nop<<<1, 32>>>();                                              // launch 4
    k_lstm<<<128, 512, SMEMB>>>(x, out);                             // launch 5 <- ncu
    k_ystats<<<640, 256>>>();
    int n = Bsz * Tt * Do;
    k_ynorm<<<(n + 255) / 256, 256>>>(gamma_out, beta_out, out);
}

// round 15
// speedup vs baseline: 7.6309x; 1.2642x over previous
#include <cuda_runtime.h>
#include <cuda_bf16.h>
#include <cuda_fp16.h>
#include <math.h>
#include <stdint.h>

#define Bsz 8192
#define Tt  128
#define Do  5
#define OFF_H ((size_t)Bsz * Tt * Do)
#define OFF_C (OFF_H + (size_t)Bsz * 128)

__device__ float4 g_s2[Tt * 128];            // folded emb-BN affine (s0,s1,s2,_)
__device__ float g_bias[512];                // b_ih+b_hh permuted to n'=4j+gate
__device__ float g_woutT[640];               // W_out^T [j][f]
__device__ float g_y[(size_t)640 * Bsz];     // pre-BN y [t*5+f][row]
__device__ float g_ymean[640];
__device__ float g_yrstd[640];
// W panels: [mat(2)][kpanel(8)] x 16KB fp16; 512 n' x 16 k each
__device__ __align__(16) char g_wp[16 * 16384];

#define SA_E  0              // e image fp16: 64 rows x 256B = 16KB
#define SA_H  16384          // h image fp16: 16KB
#define SB    32768          // ring: 4 x 16KB = 64KB -> ends 98304
#define SDST  98304          // Dst staging 64KB -> ends 163840
#define SWOUT 163840
#define SBIAS 166400
#define SMEMB 168448

__device__ __forceinline__ uint32_t s2u(const void* p) {
    uint32_t a;
    asm("{ .reg .u64 t; cvta.to.shared.u64 t, %1; cvt.u32.u64 %0, t; }" : "=r"(a) : "l"(p));
    return a;
}
__device__ __forceinline__ void ldsm4(uint32_t r[4], uint32_t a) {
    asm volatile("ldmatrix.sync.aligned.m8n8.x4.shared.b16 {%0,%1,%2,%3}, [%4];"
        : "=r"(r[0]), "=r"(r[1]), "=r"(r[2]), "=r"(r[3]) : "r"(a));
}
__device__ __forceinline__ void mma16816(float d[4], const uint32_t a[4], uint32_t b0, uint32_t b1) {
    asm volatile("mma.sync.aligned.m16n8k16.row.col.f32.f16.f16.f32 "
        "{%0,%1,%2,%3}, {%4,%5,%6,%7}, {%8,%9}, {%0,%1,%2,%3};"
        : "+f"(d[0]), "+f"(d[1]), "+f"(d[2]), "+f"(d[3])
        : "r"(a[0]), "r"(a[1]), "r"(a[2]), "r"(a[3]), "r"(b0), "r"(b1));
}
__device__ __forceinline__ float tanh_fast(float x) {
    float y;
    asm("tanh.approx.f32 %0, %1;" : "=f"(y) : "f"(x));
    return y;
}
__device__ __forceinline__ void cpa16(uint32_t dst, const void* src) {
    asm volatile("cp.async.cg.shared.global [%0], [%1], 16;" :: "r"(dst), "l"(src));
}
#define CP_COMMIT() asm volatile("cp.async.commit_group;" ::: "memory")
#define CP_WAIT0()  asm volatile("cp.async.wait_group 0;" ::: "memory")

__global__ void k_emb_stats(const float* __restrict__ x, const float* __restrict__ W_emb,
                            const float* __restrict__ b_emb, const float* __restrict__ gamma,
                            const float* __restrict__ beta) {
    int t = blockIdx.x, tid = threadIdx.x;
    float m0 = 0.f, m1 = 0.f, m00 = 0.f, m11 = 0.f, m01 = 0.f;
    for (int b = tid; b < Bsz; b += 256) {
        size_t xi = ((size_t)b * Tt + t) * 2;
        float x0 = x[xi], x1 = x[xi + 1];
        m0 += x0; m1 += x1; m00 += x0 * x0; m11 += x1 * x1; m01 += x0 * x1;
    }
    const unsigned F = 0xffffffffu;
    #pragma unroll
    for (int o = 16; o; o >>= 1) {
        m0 += __shfl_xor_sync(F, m0, o); m1 += __shfl_xor_sync(F, m1, o);
        m00 += __shfl_xor_sync(F, m00, o); m11 += __shfl_xor_sync(F, m11, o);
        m01 += __shfl_xor_sync(F, m01, o);
    }
    __shared__ float sw[8][5], mom[5];
    int w = tid >> 5, l = tid & 31;
    if (l == 0) { sw[w][0] = m0; sw[w][1] = m1; sw[w][2] = m00; sw[w][3] = m11; sw[w][4] = m01; }
    __syncthreads();
    if (tid < 5) {
        float s = 0.f;
        #pragma unroll
        for (int i = 0; i < 8; i++) s += sw[i][tid];
        mom[tid] = s * (1.0f / Bsz);
    }
    __syncthreads();
    if (tid < 128) {
        float mx0 = mom[0], mx1 = mom[1];
        float vx0 = mom[2] - mx0 * mx0, vx1 = mom[3] - mx1 * mx1, cxy = mom[4] - mx0 * mx1;
        float w0 = W_emb[tid * 2], w1 = W_emb[tid * 2 + 1];
        float mu = w0 * mx0 + w1 * mx1 + b_emb[tid];
        float var = w0 * w0 * vx0 + 2.0f * w0 * w1 * cxy + w1 * w1 * vx1;
        float gr = gamma[tid] * rsqrtf(var + 1e-5f);
        g_s2[t * 128 + tid] = make_float4(gr * w0, gr * w1,
                                          gr * (b_emb[tid] - mu) + beta[tid], 0.f);
    }
}

__global__ void k_prep(const float* __restrict__ Wih, const float* __restrict__ Whh,
                       const float* __restrict__ bih, const float* __restrict__ bhh,
                       const float* __restrict__ Wout) {
    int id = blockIdx.x * 256 + threadIdx.x;  // 131072
    int mat = id >> 16, e = id & 65535;
    int np = e >> 7, k = e & 127;
    int src = ((np & 3) * 128 + (np >> 2)) * 128 + k;
    float wv = mat ? Whh[src] : Wih[src];
    int kl = k & 15;
    int off = (mat * 8 + (k >> 4)) * 16384
            + ((np >> 3) << 8) + ((kl >> 3) << 7) + ((np & 7) << 4) + ((kl & 7) << 1);
    *(__half*)(g_wp + off) = __float2half_rn(wv);
    if (id < 512) {
        int orig = (id & 3) * 128 + (id >> 2);
        g_bias[id] = bih[orig] + bhh[orig];
    }
    if (id >= 1024 && id < 1664) {
        int idx = id - 1024;
        g_woutT[(idx & 127) * 5 + (idx >> 7)] = Wout[idx];
    }
}

__global__ void k_nop() {}

// persistent recurrence: block = 64 rows x 512 gates, 16 warps (warp tile 64x32)
// pure fp16 single-pass: gates = A_fp16 @ B_fp16 (fp32 accum)
__global__ void __launch_bounds__(512, 1) k_lstm(const float* __restrict__ x,
                                                 float* __restrict__ out) {
    extern __shared__ char sm[];
    uint32_t smb = s2u(sm);
    float* swout = (float*)(sm + SWOUT);
    int tid = threadIdx.x, lane = tid & 31, w = tid >> 5;   // w in 0..15
    int brow = blockIdx.x << 6;
    const unsigned F = 0xffffffffu;

    for (int i = tid; i < 640; i += 512) swout[i] = g_woutT[i];
    if (tid < 512) ((float*)(sm + SBIAS))[tid] = g_bias[tid];
    {
        uint4 z = make_uint4(0, 0, 0, 0);
        for (int i = tid; i < 1024; i += 512)   // zero h image (16KB)
            ((uint4*)(sm + SA_H))[i] = z;
    }

    int erow = tid >> 3, eks = tid & 7;   // e-build: 64 rows x 8 k-slices
    auto build_e = [&](int t) {
        float2 xv = *(const float2*)&x[((size_t)(brow + erow) * Tt + t) * 2];
        #pragma unroll
        for (int cc = 0; cc < 2; cc++) {
            int kc = eks * 2 + cc;
            int k0 = kc * 8;
            uint32_t wh[4];
            #pragma unroll
            for (int q = 0; q < 4; q++) {
                float4 sA = g_s2[t * 128 + k0 + q * 2];
                float4 sB = g_s2[t * 128 + k0 + q * 2 + 1];
                float e0 = fmaxf(fmaf(sA.x, xv.x, fmaf(sA.y, xv.y, sA.z)), 0.f);
                float e1 = fmaxf(fmaf(sB.x, xv.x, fmaf(sB.y, xv.y, sB.z)), 0.f);
                __half h0 = __float2half_rn(e0), h1 = __float2half_rn(e1);
                wh[q] = (uint32_t)__half_as_ushort(h0) | ((uint32_t)__half_as_ushort(h1) << 16);
            }
            int off = erow * 256 + ((kc ^ (erow & 7)) << 4);
            *(uint4*)(sm + SA_E + off) = make_uint4(wh[0], wh[1], wh[2], wh[3]);
        }
    };
    build_e(0);
    __syncthreads();

    // issue one PAIR of fp16 panels (32KB, one commit group)
    auto issuePair = [&](int P) {
        int g0 = (2 * P) & 15;              // even; panels g0, g0+1 contiguous
        const char* src = g_wp + (size_t)g0 * 16384;
        uint32_t dst = smb + SB + ((2 * P) & 3) * 16384;   // buffers {0,1} or {2,3}
        #pragma unroll
        for (int q = 0; q < 4; q++)
            cpa16(dst + q * 8192 + tid * 16, src + q * 8192 + tid * 16);
        CP_COMMIT();
    };
    issuePair(0);

    int ar = (lane & 7) | (((lane >> 3) & 1) << 3);
    int akc = lane >> 4;
    int rx = ar & 7;
    int wn0 = w << 5;
    int bnh = (lane >> 4) & 1, bkc = (lane >> 3) & 1;
    uint32_t offB[2];
    #pragma unroll
    for (int p = 0; p < 2; p++) {
        int r = wn0 + p * 16 + bnh * 8 + (lane & 7);
        offB[p] = ((r >> 3) << 8) + (bkc << 7) + ((r & 7) << 4);
    }

    float c[4][4];
    #pragma unroll
    for (int i = 0; i < 4; i++)
        #pragma unroll
        for (int j = 0; j < 4; j++) c[i][j] = 0.f;

    for (int t = 0; t < Tt; t++) {
        float acc[4][4][4];
        #pragma unroll
        for (int i = 0; i < 4; i++)
            #pragma unroll
            for (int j = 0; j < 4; j++)
                #pragma unroll
                for (int q = 0; q < 4; q++) acc[i][j][q] = 0.f;

        for (int Pl = 0; Pl < 8; Pl++) {
            int Pg = t * 8 + Pl;
            CP_WAIT0();                 // pair Pg arrived
            __syncthreads();            // all warps done reading pair Pg-1
            if (Pg + 1 < Tt * 8) issuePair(Pg + 1);
            if (Pl == 4 && t + 1 < Tt) build_e(t + 1);   // e region dead after iter 7
            #pragma unroll
            for (int u = 0; u < 2; u++) {
                int i = Pl * 2 + u;
                uint32_t aH = smb + (i < 8 ? SA_E : SA_H);
                uint32_t bH = smb + SB + (((Pg * 2 + u) & 3) * 16384);
                int kc2 = (i & 7) * 2;
                uint32_t aoff = ar * 256 + (((kc2 + akc) ^ rx) << 4);
                uint32_t ah[4][4], bh[2][4];
                #pragma unroll
                for (int mf = 0; mf < 4; mf++) ldsm4(ah[mf], aH + aoff + mf * 4096);
                #pragma unroll
                for (int p = 0; p < 2; p++) ldsm4(bh[p], bH + offB[p]);
                #pragma unroll
                for (int mf = 0; mf < 4; mf++)
                    #pragma unroll
                    for (int nf = 0; nf < 4; nf++)
                        mma16816(acc[mf][nf], ah[mf], bh[nf >> 1][(nf & 1) * 2], bh[nf >> 1][(nf & 1) * 2 + 1]);
            }
        }
        __syncthreads();   // all MMA + prior cell reads done -> stage

        // ---- staged cell, 2 slabs per phase, dedicated Dst region ----
        float* Dst = (float*)(sm + SDST);
        int rr = lane >> 2, cc2 = (lane & 3) << 1;
        #pragma unroll
        for (int half = 0; half < 2; half++) {
            #pragma unroll
            for (int s = 0; s < 2; s++) {
                int mf = half * 2 + s;
                #pragma unroll
                for (int nf = 0; nf < 4; nf++) {
                    int cb = wn0 + nf * 8 + cc2;
                    *(float2*)&Dst[(s * 16 + rr) * 512 + cb]     = make_float2(acc[mf][nf][0], acc[mf][nf][1]);
                    *(float2*)&Dst[(s * 16 + rr + 8) * 512 + cb] = make_float2(acc[mf][nf][2], acc[mf][nf][3]);
                }
            }
            __syncthreads();
            #pragma unroll
            for (int s = 0; s < 2; s++) {
                int mf = half * 2 + s;
                int rowg = mf * 16 + w;
                float ya0 = 0.f, ya1 = 0.f, ya2 = 0.f, ya3 = 0.f, ya4 = 0.f;
                float hn4[4];
                int j0 = lane * 4;
                #pragma unroll
                for (int u = 0; u < 4; u++) {
                    int j = j0 + u;
                    float4 g4 = *(float4*)&Dst[(s * 16 + w) * 512 + 4 * j];
                    float4 bv = *(float4*)(sm + SBIAS + j * 16);
                    float gi = g4.x + bv.x, gf = g4.y + bv.y, gg = g4.z + bv.z, go = g4.w + bv.w;
                    float si = fmaf(tanh_fast(0.5f * gi), 0.5f, 0.5f);
                    float sf = fmaf(tanh_fast(0.5f * gf), 0.5f, 0.5f);
                    float so = fmaf(tanh_fast(0.5f * go), 0.5f, 0.5f);
                    float tg = tanh_fast(gg);
                    float cn = sf * c[mf][u] + si * tg;
                    float tc = tanh_fast(cn);
                    float hn = so * tc;
                    c[mf][u] = cn;
                    hn4[u] = hn;
                    ya0 = fmaf(hn, swout[j * 5 + 0], ya0);
                    ya1 = fmaf(hn, swout[j * 5 + 1], ya1);
                    ya2 = fmaf(hn, swout[j * 5 + 2], ya2);
                    ya3 = fmaf(hn, swout[j * 5 + 3], ya3);
                    ya4 = fmaf(hn, swout[j * 5 + 4], ya4);
                    if (t == Tt - 1) {
                        out[OFF_H + (size_t)(brow + rowg) * 128 + j] = hn;
                        out[OFF_C + (size_t)(brow + rowg) * 128 + j] = cn;
                    }
                }
                {
                    __half h0 = __float2half_rn(hn4[0]), h1 = __float2half_rn(hn4[1]);
                    __half h2 = __float2half_rn(hn4[2]), h3 = __float2half_rn(hn4[3]);
                    uint2 wh = make_uint2(
                        (uint32_t)__half_as_ushort(h0) | ((uint32_t)__half_as_ushort(h1) << 16),
                        (uint32_t)__half_as_ushort(h2) | ((uint32_t)__half_as_ushort(h3) << 16));
                    int kc = lane >> 1;
                    int off = rowg * 256 + ((kc ^ (rowg & 7)) << 4) + (lane & 1) * 8;
                    *(uint2*)(sm + SA_H + off) = wh;
                }
                #pragma unroll
                for (int o2 = 1; o2 <= 16; o2 <<= 1) {
                    ya0 += __shfl_xor_sync(F, ya0, o2);
                    ya1 += __shfl_xor_sync(F, ya1, o2);
                    ya2 += __shfl_xor_sync(F, ya2, o2);
                    ya3 += __shfl_xor_sync(F, ya3, o2);
                    ya4 += __shfl_xor_sync(F, ya4, o2);
                }
                if (lane == 0) {
                    size_t yb = (size_t)(t * 5) * 8192 + brow + rowg;
                    g_y[yb] = ya0; g_y[yb + 8192] = ya1; g_y[yb + 16384] = ya2;
                    g_y[yb + 24576] = ya3; g_y[yb + 32768] = ya4;
                }
            }
            if (half == 0) __syncthreads();   // before restaging Dst
        }
        // new h image visible to next step's h-iterations via pair-top barriers
    }
}

__global__ void k_ystats() {
    int tf = blockIdx.x, tid = threadIdx.x;
    float s = 0.f, q = 0.f;
    for (int b = tid; b < Bsz; b += 256) {
        float v = g_y[(size_t)tf * 8192 + b];
        s += v; q += v * v;
    }
    const unsigned F = 0xffffffffu;
    #pragma unroll
    for (int o = 16; o; o >>= 1) { s += __shfl_xor_sync(F, s, o); q += __shfl_xor_sync(F, q, o); }
    __shared__ float sws[8], swq[8];
    int w = tid >> 5;
    if ((tid & 31) == 0) { sws[w] = s; swq[w] = q; }
    __syncthreads();
    if (tid == 0) {
        float S = 0.f, Q = 0.f;
        #pragma unroll
        for (int i = 0; i < 8; i++) { S += sws[i]; Q += swq[i]; }
        float mean = S * (1.0f / Bsz);
        g_ymean[tf] = mean;
        g_yrstd[tf] = rsqrtf(Q * (1.0f / Bsz) - mean * mean + 1e-5f);
    }
}
__global__ void k_ynorm(const float* __restrict__ gamma, const float* __restrict__ beta,
                        float* __restrict__ out) {
    size_t i = (size_t)blockIdx.x * 256 + threadIdx.x;
    if (i >= (size_t)Bsz * Tt * Do) return;
    size_t b = i / 640;
    int tf = (int)(i % 640);
    int f = tf % 5;
    float v = g_y[(size_t)tf * 8192 + b];
    out[i] = gamma[f] * (v - g_ymean[tf]) * g_yrstd[tf] + beta[f];
}

extern "C" void kernel_launch(void* const* d_in, const int* in_sizes, int n_in,
                              void* d_out, int out_size) {
    const float* x         = (const float*)d_in[0];
    const float* W_emb     = (const float*)d_in[1];
    const float* b_emb     = (const float*)d_in[2];
    const float* gamma_emb = (const float*)d_in[3];
    const float* beta_emb  = (const float*)d_in[4];
    const float* W_ih      = (const float*)d_in[5];
    const float* b_ih      = (const float*)d_in[6];
    const float* W_hh      = (const float*)d_in[7];
    const float* b_hh      = (const float*)d_in[8];
    const float* W_out     = (const float*)d_in[9];
    // d_in[10] = b_out: cancels exactly inside the output BatchNorm.
    const float* gamma_out = (const float*)d_in[11];
    const float* beta_out  = (const float*)d_in[12];
    float* out = (float*)d_out;

    cudaFuncSetAttribute(k_lstm, cudaFuncAttributeMaxDynamicSharedMemorySize, SMEMB);

    k_emb_stats<<<Tt, 256>>>(x, W_emb, b_emb, gamma_emb, beta_emb);  // launch 1
    k_prep<<<512, 256>>>(W_ih, W_hh, b_ih, b_hh, W_out);             // launch 2
    k_nop<<<1, 32>>>();                                              // launch 3
    k_nop<<<1, 32>>>();                                              // launch 4
    k_nop<<<1, 32>>>();                                              // launch 5
    k_lstm<<<128, 512, SMEMB>>>(x, out);                             // launch 6 <- ncu
    k_ystats<<<640, 256>>>();
    int n = Bsz * Tt * Do;
    k_ynorm<<<(n + 255) / 256, 256>>>(gamma_out, beta_out, out);
}

// round 16
// speedup vs baseline: 7.8502x; 1.0287x over previous
#include <cuda_runtime.h>
#include <cuda_bf16.h>
#include <cuda_fp16.h>
#include <math.h>
#include <stdint.h>

#define Bsz 8192
#define Tt  128
#define Do  5
#define OFF_H ((size_t)Bsz * Tt * Do)
#define OFF_C (OFF_H + (size_t)Bsz * 128)

__device__ float4 g_s2[Tt * 128];            // folded emb-BN affine (s0,s1,s2,_)
__device__ float g_bias[512];                // b_ih+b_hh permuted to n'=4j+gate
__device__ float g_woutT[640];               // W_out^T [j][f]
__device__ float g_y[(size_t)640 * Bsz];     // pre-BN y [t*5+f][row]
__device__ float g_ymean[640];
__device__ float g_yrstd[640];
// W panels: [mat(2)][kpanel(8)] x 16KB fp16; 512 n' x 16 k each
__device__ __align__(16) char g_wp[16 * 16384];

#define SA_E  0              // e image fp16: 64 rows x 256B = 16KB
#define SA_H  16384          // h image fp16: 16KB
#define SB    32768          // ring: 2 x 64KB groups -> ends 163840
#define SDST  98304          // Dst staging = ring buffer 1 (dead during cell)
#define SWOUT 163840
#define SBIAS 166400
#define SMEMB 168448

__device__ __forceinline__ uint32_t s2u(const void* p) {
    uint32_t a;
    asm("{ .reg .u64 t; cvta.to.shared.u64 t, %1; cvt.u32.u64 %0, t; }" : "=r"(a) : "l"(p));
    return a;
}
__device__ __forceinline__ void ldsm4(uint32_t r[4], uint32_t a) {
    asm volatile("ldmatrix.sync.aligned.m8n8.x4.shared.b16 {%0,%1,%2,%3}, [%4];"
        : "=r"(r[0]), "=r"(r[1]), "=r"(r[2]), "=r"(r[3]) : "r"(a));
}
__device__ __forceinline__ void mma16816(float d[4], const uint32_t a[4], uint32_t b0, uint32_t b1) {
    asm volatile("mma.sync.aligned.m16n8k16.row.col.f32.f16.f16.f32 "
        "{%0,%1,%2,%3}, {%4,%5,%6,%7}, {%8,%9}, {%0,%1,%2,%3};"
        : "+f"(d[0]), "+f"(d[1]), "+f"(d[2]), "+f"(d[3])
        : "r"(a[0]), "r"(a[1]), "r"(a[2]), "r"(a[3]), "r"(b0), "r"(b1));
}
__device__ __forceinline__ float tanh_fast(float x) {
    float y;
    asm("tanh.approx.f32 %0, %1;" : "=f"(y) : "f"(x));
    return y;
}
__device__ __forceinline__ void cpa16(uint32_t dst, const void* src) {
    asm volatile("cp.async.cg.shared.global [%0], [%1], 16;" :: "r"(dst), "l"(src));
}
#define CP_COMMIT() asm volatile("cp.async.commit_group;" ::: "memory")
#define CP_WAIT0()  asm volatile("cp.async.wait_group 0;" ::: "memory")

__global__ void k_emb_stats(const float* __restrict__ x, const float* __restrict__ W_emb,
                            const float* __restrict__ b_emb, const float* __restrict__ gamma,
                            const float* __restrict__ beta) {
    int t = blockIdx.x, tid = threadIdx.x;
    float m0 = 0.f, m1 = 0.f, m00 = 0.f, m11 = 0.f, m01 = 0.f;
    for (int b = tid; b < Bsz; b += 256) {
        size_t xi = ((size_t)b * Tt + t) * 2;
        float x0 = x[xi], x1 = x[xi + 1];
        m0 += x0; m1 += x1; m00 += x0 * x0; m11 += x1 * x1; m01 += x0 * x1;
    }
    const unsigned F = 0xffffffffu;
    #pragma unroll
    for (int o = 16; o; o >>= 1) {
        m0 += __shfl_xor_sync(F, m0, o); m1 += __shfl_xor_sync(F, m1, o);
        m00 += __shfl_xor_sync(F, m00, o); m11 += __shfl_xor_sync(F, m11, o);
        m01 += __shfl_xor_sync(F, m01, o);
    }
    __shared__ float sw[8][5], mom[5];
    int w = tid >> 5, l = tid & 31;
    if (l == 0) { sw[w][0] = m0; sw[w][1] = m1; sw[w][2] = m00; sw[w][3] = m11; sw[w][4] = m01; }
    __syncthreads();
    if (tid < 5) {
        float s = 0.f;
        #pragma unroll
        for (int i = 0; i < 8; i++) s += sw[i][tid];
        mom[tid] = s * (1.0f / Bsz);
    }
    __syncthreads();
    if (tid < 128) {
        float mx0 = mom[0], mx1 = mom[1];
        float vx0 = mom[2] - mx0 * mx0, vx1 = mom[3] - mx1 * mx1, cxy = mom[4] - mx0 * mx1;
        float w0 = W_emb[tid * 2], w1 = W_emb[tid * 2 + 1];
        float mu = w0 * mx0 + w1 * mx1 + b_emb[tid];
        float var = w0 * w0 * vx0 + 2.0f * w0 * w1 * cxy + w1 * w1 * vx1;
        float gr = gamma[tid] * rsqrtf(var + 1e-5f);
        g_s2[t * 128 + tid] = make_float4(gr * w0, gr * w1,
                                          gr * (b_emb[tid] - mu) + beta[tid], 0.f);
    }
}

__global__ void k_prep(const float* __restrict__ Wih, const float* __restrict__ Whh,
                       const float* __restrict__ bih, const float* __restrict__ bhh,
                       const float* __restrict__ Wout) {
    int id = blockIdx.x * 256 + threadIdx.x;  // 131072
    int mat = id >> 16, e = id & 65535;
    int np = e >> 7, k = e & 127;
    int src = ((np & 3) * 128 + (np >> 2)) * 128 + k;
    float wv = mat ? Whh[src] : Wih[src];
    int kl = k & 15;
    int off = (mat * 8 + (k >> 4)) * 16384
            + ((np >> 3) << 8) + ((kl >> 3) << 7) + ((np & 7) << 4) + ((kl & 7) << 1);
    *(__half*)(g_wp + off) = __float2half_rn(wv);
    if (id < 512) {
        int orig = (id & 3) * 128 + (id >> 2);
        g_bias[id] = bih[orig] + bhh[orig];
    }
    if (id >= 1024 && id < 1664) {
        int idx = id - 1024;
        g_woutT[(idx & 127) * 5 + (idx >> 7)] = Wout[idx];
    }
}

// persistent recurrence: block = 64 rows x 512 gates, 16 warps (warp tile 64x32)
// pure fp16 single-pass: gates = A_fp16 @ B_fp16 (fp32 accum)
__global__ void __launch_bounds__(512, 1) k_lstm(const float* __restrict__ x,
                                                 float* __restrict__ out) {
    extern __shared__ char sm[];
    uint32_t smb = s2u(sm);
    float* swout = (float*)(sm + SWOUT);
    int tid = threadIdx.x, lane = tid & 31, w = tid >> 5;   // w in 0..15
    int brow = blockIdx.x << 6;
    const unsigned F = 0xffffffffu;

    for (int i = tid; i < 640; i += 512) swout[i] = g_woutT[i];
    if (tid < 512) ((float*)(sm + SBIAS))[tid] = g_bias[tid];
    {
        uint4 z = make_uint4(0, 0, 0, 0);
        for (int i = tid; i < 1024; i += 512)   // zero h image (16KB)
            ((uint4*)(sm + SA_H))[i] = z;
    }

    int erow = tid >> 3, eks = tid & 7;   // e-build: 64 rows x 8 k-slices
    auto build_e = [&](int t) {
        float2 xv = *(const float2*)&x[((size_t)(brow + erow) * Tt + t) * 2];
        #pragma unroll
        for (int cc = 0; cc < 2; cc++) {
            int kc = eks * 2 + cc;
            int k0 = kc * 8;
            uint32_t wh[4];
            #pragma unroll
            for (int q = 0; q < 4; q++) {
                float4 sA = g_s2[t * 128 + k0 + q * 2];
                float4 sB = g_s2[t * 128 + k0 + q * 2 + 1];
                float e0 = fmaxf(fmaf(sA.x, xv.x, fmaf(sA.y, xv.y, sA.z)), 0.f);
                float e1 = fmaxf(fmaf(sB.x, xv.x, fmaf(sB.y, xv.y, sB.z)), 0.f);
                __half h0 = __float2half_rn(e0), h1 = __float2half_rn(e1);
                wh[q] = (uint32_t)__half_as_ushort(h0) | ((uint32_t)__half_as_ushort(h1) << 16);
            }
            int off = erow * 256 + ((kc ^ (erow & 7)) << 4);
            *(uint4*)(sm + SA_E + off) = make_uint4(wh[0], wh[1], wh[2], wh[3]);
        }
    };
    build_e(0);
    __syncthreads();

    // issue one GROUP of 4 fp16 panels (64KB, one commit group)
    auto issueGroup = [&](int G) {
        const char* src = g_wp + (size_t)((4 * G) & 15) * 16384;
        uint32_t dst = smb + SB + (G & 1) * 65536;
        #pragma unroll
        for (int q = 0; q < 8; q++)
            cpa16(dst + q * 8192 + tid * 16, src + q * 8192 + tid * 16);
        CP_COMMIT();
    };
    issueGroup(0);

    int ar = (lane & 7) | (((lane >> 3) & 1) << 3);
    int akc = lane >> 4;
    int rx = ar & 7;
    int wn0 = w << 5;
    int bnh = (lane >> 4) & 1, bkc = (lane >> 3) & 1;
    uint32_t offB[2];
    #pragma unroll
    for (int p = 0; p < 2; p++) {
        int r = wn0 + p * 16 + bnh * 8 + (lane & 7);
        offB[p] = ((r >> 3) << 8) + (bkc << 7) + ((r & 7) << 4);
    }

    float c[4][4];
    #pragma unroll
    for (int i = 0; i < 4; i++)
        #pragma unroll
        for (int j = 0; j < 4; j++) c[i][j] = 0.f;

    for (int t = 0; t < Tt; t++) {
        float acc[4][4][4];
        #pragma unroll
        for (int i = 0; i < 4; i++)
            #pragma unroll
            for (int j = 0; j < 4; j++)
                #pragma unroll
                for (int q = 0; q < 4; q++) acc[i][j][q] = 0.f;

        for (int g = 0; g < 4; g++) {
            int G = t * 4 + g;
            CP_WAIT0();                 // group G arrived
            __syncthreads();            // all warps done reading group G-1
            if (G + 1 < Tt * 4) issueGroup(G + 1);
            if (g == 2 && t + 1 < Tt) build_e(t + 1);   // e region dead after i=7
            #pragma unroll
            for (int u = 0; u < 4; u++) {
                int i = g * 4 + u;
                uint32_t aH = smb + (i < 8 ? SA_E : SA_H);
                uint32_t bH = smb + SB + (G & 1) * 65536 + u * 16384;
                int kc2 = (i & 7) * 2;
                uint32_t aoff = ar * 256 + (((kc2 + akc) ^ rx) << 4);
                uint32_t ah[4][4], bh[2][4];
                #pragma unroll
                for (int mf = 0; mf < 4; mf++) ldsm4(ah[mf], aH + aoff + mf * 4096);
                #pragma unroll
                for (int p = 0; p < 2; p++) ldsm4(bh[p], bH + offB[p]);
                #pragma unroll
                for (int mf = 0; mf < 4; mf++)
                    #pragma unroll
                    for (int nf = 0; nf < 4; nf++)
                        mma16816(acc[mf][nf], ah[mf], bh[nf >> 1][(nf & 1) * 2], bh[nf >> 1][(nf & 1) * 2 + 1]);
            }
        }
        __syncthreads();   // all MMA reads done; ring buffer 1 dead -> Dst

        // ---- staged cell, 2 slabs per phase, Dst = dead ring buffer 1 ----
        float* Dst = (float*)(sm + SDST);
        int rr = lane >> 2, cc2 = (lane & 3) << 1;
        #pragma unroll
        for (int half = 0; half < 2; half++) {
            #pragma unroll
            for (int s = 0; s < 2; s++) {
                int mf = half * 2 + s;
                #pragma unroll
                for (int nf = 0; nf < 4; nf++) {
                    int cb = wn0 + nf * 8 + cc2;
                    *(float2*)&Dst[(s * 16 + rr) * 512 + cb]     = make_float2(acc[mf][nf][0], acc[mf][nf][1]);
                    *(float2*)&Dst[(s * 16 + rr + 8) * 512 + cb] = make_float2(acc[mf][nf][2], acc[mf][nf][3]);
                }
            }
            __syncthreads();
            #pragma unroll
            for (int s = 0; s < 2; s++) {
                int mf = half * 2 + s;
                int rowg = mf * 16 + w;
                float ya0 = 0.f, ya1 = 0.f, ya2 = 0.f, ya3 = 0.f, ya4 = 0.f;
                float hn4[4];
                int j0 = lane * 4;
                #pragma unroll
                for (int u = 0; u < 4; u++) {
                    int j = j0 + u;
                    float4 g4 = *(float4*)&Dst[(s * 16 + w) * 512 + 4 * j];
                    float4 bv = *(float4*)(sm + SBIAS + j * 16);
                    float gi = g4.x + bv.x, gf = g4.y + bv.y, gg = g4.z + bv.z, go = g4.w + bv.w;
                    float si = fmaf(tanh_fast(0.5f * gi), 0.5f, 0.5f);
                    float sf = fmaf(tanh_fast(0.5f * gf), 0.5f, 0.5f);
                    float so = fmaf(tanh_fast(0.5f * go), 0.5f, 0.5f);
                    float tg = tanh_fast(gg);
                    float cn = sf * c[mf][u] + si * tg;
                    float tc = tanh_fast(cn);
                    float hn = so * tc;
                    c[mf][u] = cn;
                    hn4[u] = hn;
                    ya0 = fmaf(hn, swout[j * 5 + 0], ya0);
                    ya1 = fmaf(hn, swout[j * 5 + 1], ya1);
                    ya2 = fmaf(hn, swout[j * 5 + 2], ya2);
                    ya3 = fmaf(hn, swout[j * 5 + 3], ya3);
                    ya4 = fmaf(hn, swout[j * 5 + 4], ya4);
                    if (t == Tt - 1) {
                        out[OFF_H + (size_t)(brow + rowg) * 128 + j] = hn;
                        out[OFF_C + (size_t)(brow + rowg) * 128 + j] = cn;
                    }
                }
                {
                    __half h0 = __float2half_rn(hn4[0]), h1 = __float2half_rn(hn4[1]);
                    __half h2 = __float2half_rn(hn4[2]), h3 = __float2half_rn(hn4[3]);
                    uint2 wh = make_uint2(
                        (uint32_t)__half_as_ushort(h0) | ((uint32_t)__half_as_ushort(h1) << 16),
                        (uint32_t)__half_as_ushort(h2) | ((uint32_t)__half_as_ushort(h3) << 16));
                    int kc = lane >> 1;
                    int off = rowg * 256 + ((kc ^ (rowg & 7)) << 4) + (lane & 1) * 8;
                    *(uint2*)(sm + SA_H + off) = wh;
                }
                #pragma unroll
                for (int o2 = 1; o2 <= 16; o2 <<= 1) {
                    ya0 += __shfl_xor_sync(F, ya0, o2);
                    ya1 += __shfl_xor_sync(F, ya1, o2);
                    ya2 += __shfl_xor_sync(F, ya2, o2);
                    ya3 += __shfl_xor_sync(F, ya3, o2);
                    ya4 += __shfl_xor_sync(F, ya4, o2);
                }
                if (lane == 0) {
                    size_t yb = (size_t)(t * 5) * 8192 + brow + rowg;
                    g_y[yb] = ya0; g_y[yb + 8192] = ya1; g_y[yb + 16384] = ya2;
                    g_y[yb + 24576] = ya3; g_y[yb + 32768] = ya4;
                }
            }
            if (half == 0) __syncthreads();   // before restaging Dst
        }
        // new h image ordered before next step's h-iterations by group-top barriers
    }
}

__global__ void k_ystats() {
    int tf = blockIdx.x, tid = threadIdx.x;
    float s = 0.f, q = 0.f;
    for (int b = tid; b < Bsz; b += 256) {
        float v = g_y[(size_t)tf * 8192 + b];
        s += v; q += v * v;
    }
    const unsigned F = 0xffffffffu;
    #pragma unroll
    for (int o = 16; o; o >>= 1) { s += __shfl_xor_sync(F, s, o); q += __shfl_xor_sync(F, q, o); }
    __shared__ float sws[8], swq[8];
    int w = tid >> 5;
    if ((tid & 31) == 0) { sws[w] = s; swq[w] = q; }
    __syncthreads();
    if (tid == 0) {
        float S = 0.f, Q = 0.f;
        #pragma unroll
        for (int i = 0; i < 8; i++) { S += sws[i]; Q += swq[i]; }
        float mean = S * (1.0f / Bsz);
        g_ymean[tf] = mean;
        g_yrstd[tf] = rsqrtf(Q * (1.0f / Bsz) - mean * mean + 1e-5f);
    }
}
__global__ void k_ynorm(const float* __restrict__ gamma, const float* __restrict__ beta,
                        float* __restrict__ out) {
    size_t i = (size_t)blockIdx.x * 256 + threadIdx.x;
    if (i >= (size_t)Bsz * Tt * Do) return;
    size_t b = i / 640;
    int tf = (int)(i % 640);
    int f = tf % 5;
    float v = g_y[(size_t)tf * 8192 + b];
    out[i] = gamma[f] * (v - g_ymean[tf]) * g_yrstd[tf] + beta[f];
}

extern "C" void kernel_launch(void* const* d_in, const int* in_sizes, int n_in,
                              void* d_out, int out_size) {
    const float* x         = (const float*)d_in[0];
    const float* W_emb     = (const float*)d_in[1];
    const float* b_emb     = (const float*)d_in[2];
    const float* gamma_emb = (const float*)d_in[3];
    const float* beta_emb  = (const float*)d_in[4];
    const float* W_ih      = (const float*)d_in[5];
    const float* b_ih      = (const float*)d_in[6];
    const float* W_hh      = (const float*)d_in[7];
    const float* b_hh      = (const float*)d_in[8];
    const float* W_out     = (const float*)d_in[9];
    // d_in[10] = b_out: cancels exactly inside the output BatchNorm.
    const float* gamma_out = (const float*)d_in[11];
    const float* beta_out  = (const float*)d_in[12];
    float* out = (float*)d_out;

    cudaFuncSetAttribute(k_lstm, cudaFuncAttributeMaxDynamicSharedMemorySize, SMEMB);

    k_emb_stats<<<Tt, 256>>>(x, W_emb, b_emb, gamma_emb, beta_emb);
    k_prep<<<512, 256>>>(W_ih, W_hh, b_ih, b_hh, W_out);
    k_lstm<<<128, 512, SMEMB>>>(x, out);
    k_ystats<<<640, 256>>>();
    int n = Bsz * Tt * Do;
    k_ynorm<<<(n + 255) / 256, 256>>>(gamma_out, beta_out, out);
}